// round 10
// baseline (speedup 1.0000x reference)
#include <cuda_runtime.h>
#include <cuda_fp16.h>
#include <cstdint>
#include <math.h>

#define B_DIM 8
#define S_DIM 2048
#define H_DIM 512
#define NROWS (B_DIM * S_DIM)          // 16384
#define NSTACK (3 * H_DIM)             // 1536

// ---------------- scratch (device globals; no allocations allowed) ----------
__device__ float g_pe[S_DIM * H_DIM];
__device__ float g_bias[NSTACK];
__device__ __half g_xh[NROWS * H_DIM], g_xl[NROWS * H_DIM];
__device__ __half g_wh[NSTACK * H_DIM], g_wl[NSTACK * H_DIM];   // stacked Wq,Wk,Wv
__device__ __half g_qh[NROWS * H_DIM], g_ql[NROWS * H_DIM];
__device__ __half g_kh[NROWS * H_DIM], g_kl[NROWS * H_DIM];
__device__ __half g_vt[H_DIM * NROWS];                          // v transposed, fp16
__device__ float g_sc[(long long)B_DIM * S_DIM * S_DIM];        // 134 MB
__device__ __half g_ph[(long long)B_DIM * S_DIM * S_DIM];       // probs fp16

// ---------------- helpers ----------------------------------------------
__device__ __forceinline__ uint32_t smem_u32(const void* p) {
    uint32_t a;
    asm("{ .reg .u64 t; cvta.to.shared.u64 t, %1; cvt.u32.u64 %0, t; }" : "=r"(a) : "l"(p));
    return a;
}
__device__ __forceinline__ void cp16(uint32_t dst, const void* src) {
    asm volatile("cp.async.cg.shared.global [%0], [%1], 16;"
                 :: "r"(dst), "l"(__cvta_generic_to_global(src)));
}
#define CP_COMMIT() asm volatile("cp.async.commit_group;" ::: "memory")
#define CP_WAIT_0() asm volatile("cp.async.wait_group 0;" ::: "memory")

__device__ __forceinline__ void ldsm4(uint32_t& r0, uint32_t& r1, uint32_t& r2, uint32_t& r3,
                                      uint32_t addr) {
    asm volatile("ldmatrix.sync.aligned.m8n8.x4.shared.b16 {%0,%1,%2,%3}, [%4];"
                 : "=r"(r0), "=r"(r1), "=r"(r2), "=r"(r3) : "r"(addr));
}
__device__ __forceinline__ void mma16816(float* c, const uint32_t* a, const uint32_t* b) {
    asm volatile(
        "mma.sync.aligned.m16n8k16.row.col.f32.f16.f16.f32 "
        "{%0,%1,%2,%3}, {%4,%5,%6,%7}, {%8,%9}, {%0,%1,%2,%3};"
        : "+f"(c[0]), "+f"(c[1]), "+f"(c[2]), "+f"(c[3])
        : "r"(a[0]), "r"(a[1]), "r"(a[2]), "r"(a[3]), "r"(b[0]), "r"(b[1]));
}
__device__ __forceinline__ void split2h(float v, unsigned short& h, unsigned short& l) {
    __half hh = __float2half_rn(v);
    __half ll = __float2half_rn(v - __half2float(hh));
    h = __half_as_ushort(hh);
    l = __half_as_ushort(ll);
}

// ---------------- split-fp16 HMMA GEMM: C = A * B^T -------------------------
// Block tile 128x128, BK=32, 128 threads (2x2 warps), warp tile 64x64.
// SMEM rows: pitch 80B (64B data + 16B pad) -> conflict-free ldsm.
// Single-sync double buffer: [load c+1][compute c][wait+sync].
struct GemmParams {
    const __half *Ah, *Al, *Bh, *Bl;
    const float* bias;
    long long aBatch, bBatch;
    int aRow, bRow, K;
    __half *qh, *ql, *kh, *kl, *vt;    // MODE 0 outputs
    float* outF;                        // MODE 2 output
    long long oBatch;
    int oRow;
};

#define PITCH   80
#define TILE_SZ (128 * PITCH)           // 10240

template<int NPROD, int MODE>   // MODE: 0 = fused QKV epilogue, 2 = fp32 out
__global__ __launch_bounds__(128, 2) void tc_gemm(GemmParams p) {
    constexpr int NT = (NPROD == 3) ? 4 : 2;
    constexpr int STAGE = NT * TILE_SZ;
    extern __shared__ char smem[];
    uint32_t sbase = smem_u32(smem);

    const int tid = threadIdx.x;
    const int wid = tid >> 5, lane = tid & 31;
    const int wm = wid & 1, wn = wid >> 1;          // 2x2 warps, warp tile 64x64

    const int bm = blockIdx.y * 128, bn = blockIdx.x * 128, z = blockIdx.z;
    const __half* Ah = p.Ah + (long long)z * p.aBatch;
    const __half* Al = p.Al + (long long)z * p.aBatch;
    const __half* Bh = p.Bh + (long long)z * p.bBatch;
    const __half* Bl = p.Bl + (long long)z * p.bBatch;
    const int aRow = p.aRow, bRow = p.bRow;

    const int nc = p.K >> 5;

    auto load_chunk = [&](int c, int s) {
        uint32_t st = sbase + s * STAGE;
        long long kofs = (long long)c * 32;
#pragma unroll
        for (int t = 0; t < NT; t++) {
            const __half* src;
            int rbase, rstride;
            if (NPROD == 3) {
                if (t == 0)      { src = Ah; rbase = bm; rstride = aRow; }
                else if (t == 1) { src = Al; rbase = bm; rstride = aRow; }
                else if (t == 2) { src = Bh; rbase = bn; rstride = bRow; }
                else             { src = Bl; rbase = bn; rstride = bRow; }
            } else {
                if (t == 0)      { src = Ah; rbase = bm; rstride = aRow; }
                else             { src = Bh; rbase = bn; rstride = bRow; }
            }
            uint32_t tb = st + t * TILE_SZ;
#pragma unroll
            for (int it = 0; it < 4; it++) {
                int u = tid + it * 128;            // 512 units per tile
                int row = u >> 2, ch = u & 3;
                cp16(tb + row * PITCH + ch * 16,
                     src + (long long)(rbase + row) * rstride + kofs + ch * 8);
            }
        }
        CP_COMMIT();
    };

    float acc[4][8][4];
#pragma unroll
    for (int i = 0; i < 4; i++)
#pragma unroll
        for (int j = 0; j < 8; j++)
#pragma unroll
            for (int r = 0; r < 4; r++) acc[i][j][r] = 0.f;

    // prologue: stage 0 ready before loop
    load_chunk(0, 0);
    CP_WAIT_0();
    __syncthreads();

    for (int c = 0; c < nc; c++) {
        int s = c & 1;
        if (c + 1 < nc) load_chunk(c + 1, s ^ 1);

        uint32_t st = sbase + s * STAGE;
        uint32_t aHB = st, aLB = st + TILE_SZ;
        uint32_t bHB = st + (NT - 2) * TILE_SZ;
        uint32_t bLB = st + (NT - 1) * TILE_SZ;
        if (NPROD == 1) bHB = st + TILE_SZ;

#pragma unroll
        for (int ks = 0; ks < 2; ks++) {
            const int chcol = (ks * 2 + (lane >> 4)) * 16;
            uint32_t ah[4][4], al[4][4];
#pragma unroll
            for (int t = 0; t < 4; t++) {
                int row = wm * 64 + t * 16 + (lane & 15);
                uint32_t off = row * PITCH + chcol;
                ldsm4(ah[t][0], ah[t][1], ah[t][2], ah[t][3], aHB + off);
                if (NPROD == 3)
                    ldsm4(al[t][0], al[t][1], al[t][2], al[t][3], aLB + off);
            }
#pragma unroll
            for (int jh = 0; jh < 2; jh++) {
                uint32_t bh[4][2], bl[4][2];
#pragma unroll
                for (int jj = 0; jj < 2; jj++) {
                    int row = wn * 64 + (jh * 2 + jj) * 16 + (lane & 15);
                    uint32_t off = row * PITCH + chcol;
                    uint32_t r0, r1, r2, r3;
                    ldsm4(r0, r1, r2, r3, bHB + off);
                    bh[jj * 2][0] = r0; bh[jj * 2][1] = r2;
                    bh[jj * 2 + 1][0] = r1; bh[jj * 2 + 1][1] = r3;
                    if (NPROD == 3) {
                        ldsm4(r0, r1, r2, r3, bLB + off);
                        bl[jj * 2][0] = r0; bl[jj * 2][1] = r2;
                        bl[jj * 2 + 1][0] = r1; bl[jj * 2 + 1][1] = r3;
                    }
                }
#pragma unroll
                for (int i = 0; i < 4; i++)
#pragma unroll
                    for (int j4 = 0; j4 < 4; j4++)
                        mma16816(acc[i][jh * 4 + j4], ah[i], bh[j4]);
                if (NPROD == 3) {
#pragma unroll
                    for (int i = 0; i < 4; i++)
#pragma unroll
                        for (int j4 = 0; j4 < 4; j4++)
                            mma16816(acc[i][jh * 4 + j4], ah[i], bl[j4]);
#pragma unroll
                    for (int i = 0; i < 4; i++)
#pragma unroll
                        for (int j4 = 0; j4 < 4; j4++)
                            mma16816(acc[i][jh * 4 + j4], al[i], bh[j4]);
                }
            }
        }
        CP_WAIT_0();
        __syncthreads();
    }

    // --------- epilogue ---------
    if (MODE == 2) {
        float* o0 = p.outF + (long long)z * p.oBatch;
        const int mB = bm + wm * 64 + (lane >> 2);
        const int nB = bn + wn * 64 + (lane & 3) * 2;
#pragma unroll
        for (int i = 0; i < 4; i++)
#pragma unroll
            for (int j = 0; j < 8; j++) {
                int m = mB + i * 16, n = nB + j * 8;
                *(float2*)(o0 + (long long)m * p.oRow + n)       = make_float2(acc[i][j][0], acc[i][j][1]);
                *(float2*)(o0 + (long long)(m + 8) * p.oRow + n) = make_float2(acc[i][j][2], acc[i][j][3]);
            }
    } else {
        const int sel = bn >> 9;                    // 0=Q 1=K 2=V
        if (sel < 2) {
            __half* o0 = sel ? p.kh : p.qh;
            __half* o1 = sel ? p.kl : p.ql;
            const int mB = bm + wm * 64 + (lane >> 2);
            const int nW = wn * 64 + (lane & 3) * 2;
#pragma unroll
            for (int i = 0; i < 4; i++)
#pragma unroll
                for (int j = 0; j < 8; j++) {
                    int m = mB + i * 16;
                    int nl = (bn & 511) + nW + j * 8;
                    float b0 = p.bias[bn + nW + j * 8], b1 = p.bias[bn + nW + j * 8 + 1];
                    unsigned short h0, l0, h1, l1;
#pragma unroll
                    for (int hf = 0; hf < 2; hf++) {
                        int mm = m + hf * 8;
                        split2h(acc[i][j][hf * 2 + 0] + b0, h0, l0);
                        split2h(acc[i][j][hf * 2 + 1] + b1, h1, l1);
                        long long a = (long long)mm * H_DIM + nl;
                        *(ushort2*)(o0 + a) = make_ushort2(h0, h1);
                        *(ushort2*)(o1 + a) = make_ushort2(l0, l1);
                    }
                }
        } else {
            // V: transposed fp16 out via smem staging [128][129] u32
            uint32_t* stg = (uint32_t*)smem;
            __syncthreads();
#pragma unroll
            for (int i = 0; i < 4; i++)
#pragma unroll
                for (int j = 0; j < 8; j++)
#pragma unroll
                    for (int r = 0; r < 4; r++) {
                        int ml = wm * 64 + i * 16 + (r >> 1) * 8 + (lane >> 2);
                        int nl = wn * 64 + j * 8 + (lane & 3) * 2 + (r & 1);
                        float v = acc[i][j][r] + p.bias[bn + nl];
                        stg[ml * 129 + nl] = (uint32_t)__half_as_ushort(__float2half_rn(v));
                    }
            __syncthreads();
            // 128 threads: thread owns one column, writes 128 rows
            int col = tid;
            int n = (bn & 511) + col;
            long long base = (long long)n * NROWS + bm;
#pragma unroll
            for (int r = 0; r < 128; r += 2) {
                uint32_t w0 = stg[r * 129 + col];
                uint32_t w1 = stg[(r + 1) * 129 + col];
                *(ushort2*)(p.vt + base + r) =
                    make_ushort2((unsigned short)w0, (unsigned short)w1);
            }
        }
    }
}

// ---------------- prep: pe table + stacked weight splits + stacked bias ------
__global__ void prep_kernel(const float* __restrict__ Wq, const float* __restrict__ Wk,
                            const float* __restrict__ Wv,
                            const float* __restrict__ bq, const float* __restrict__ bk,
                            const float* __restrict__ bv,
                            float* __restrict__ pe, float* __restrict__ bias,
                            __half* __restrict__ wh, __half* __restrict__ wl) {
    int b = blockIdx.x, t = threadIdx.x;
    if (b < 4096) {                                    // pe: 1M elements
        int idx = b * 256 + t;
        int h = idx & (H_DIM - 1);
        int s = idx >> 9;
        int j = (h < H_DIM / 2) ? h : h - H_DIM / 2;
        double d   = exp(-((double)(2 * j)) * (log(10000.0) / (double)H_DIM));
        double ang = (double)s * d;
        pe[idx] = (float)((h < H_DIM / 2) ? sin(ang) : cos(ang));
    } else if (b < 4096 + 3072) {                      // stacked weights 1536x512
        int idx = (b - 4096) * 256 + t;
        int w = idx >> 18;
        int off = idx & 262143;
        const float* W = (w == 0) ? Wq : (w == 1) ? Wk : Wv;
        unsigned short h, l;
        split2h(W[off], h, l);
        wh[idx] = __ushort_as_half(h);
        wl[idx] = __ushort_as_half(l);
    } else {                                           // stacked bias 1536
        int i = (b - 4096 - 3072) * 256 + t;
        if (i < NSTACK)
            bias[i] = (i < 512) ? bq[i] : (i < 1024) ? bk[i - 512] : bv[i - 1024];
    }
}

__global__ void conv_x_kernel(const float* __restrict__ in, const float* __restrict__ pe,
                              __half* __restrict__ xh, __half* __restrict__ xl) {
    int i = blockIdx.x * blockDim.x + threadIdx.x;
    if (i >= NROWS * H_DIM) return;
    float v = in[i] + pe[i & (S_DIM * H_DIM - 1)];
    unsigned short h, l;
    split2h(v, h, l);
    xh[i] = __ushort_as_half(h);
    xl[i] = __ushort_as_half(l);
}

// ---------------- softmax: fp32 in, fp16 out ---------------------------------
__global__ __launch_bounds__(256) void softmax_kernel(const float* __restrict__ sc,
                                                      __half* __restrict__ ph) {
    const float* row = sc + (long long)blockIdx.x * S_DIM;
    long long obase = (long long)blockIdx.x * S_DIM + threadIdx.x * 8;
    int tid = threadIdx.x;
    __shared__ float red[256];

    float4 a = *(const float4*)(row + tid * 8);
    float4 b = *(const float4*)(row + tid * 8 + 4);
    float m = fmaxf(fmaxf(fmaxf(a.x, a.y), fmaxf(a.z, a.w)),
                    fmaxf(fmaxf(b.x, b.y), fmaxf(b.z, b.w)));
    red[tid] = m; __syncthreads();
    for (int s = 128; s > 0; s >>= 1) {
        if (tid < s) red[tid] = fmaxf(red[tid], red[tid + s]);
        __syncthreads();
    }
    m = red[0]; __syncthreads();

    float e[8];
    e[0] = expf(a.x - m); e[1] = expf(a.y - m); e[2] = expf(a.z - m); e[3] = expf(a.w - m);
    e[4] = expf(b.x - m); e[5] = expf(b.y - m); e[6] = expf(b.z - m); e[7] = expf(b.w - m);
    float sum = 0.f;
#pragma unroll
    for (int i = 0; i < 8; i++) sum += e[i];
    red[tid] = sum; __syncthreads();
    for (int s = 128; s > 0; s >>= 1) {
        if (tid < s) red[tid] += red[tid + s];
        __syncthreads();
    }
    float inv = 1.f / red[0];
#pragma unroll
    for (int i = 0; i < 4; i++) {
        __half2 w2 = __floats2half2_rn(e[i * 2] * inv, e[i * 2 + 1] * inv);
        *(__half2*)(ph + obase + i * 2) = w2;
    }
}

// ---------------- launch ----------------------------------------------------
extern "C" void kernel_launch(void* const* d_in, const int* in_sizes, int n_in,
                              void* d_out, int out_size) {
    const float* in_e = (const float*)d_in[0];
    const float* Wq   = (const float*)d_in[1];
    const float* bq   = (const float*)d_in[2];
    const float* Wk   = (const float*)d_in[3];
    const float* bk   = (const float*)d_in[4];
    const float* Wv   = (const float*)d_in[5];
    const float* bv   = (const float*)d_in[6];
    float* out = (float*)d_out;

    const int SMEM3 = 2 * 4 * TILE_SZ;   // 81920
    const int SMEM1 = 2 * 2 * TILE_SZ;   // 40960
    cudaFuncSetAttribute(tc_gemm<3,0>, cudaFuncAttributeMaxDynamicSharedMemorySize, SMEM3);
    cudaFuncSetAttribute(tc_gemm<3,2>, cudaFuncAttributeMaxDynamicSharedMemorySize, SMEM3);
    cudaFuncSetAttribute(tc_gemm<1,2>, cudaFuncAttributeMaxDynamicSharedMemorySize, SMEM1);

#define SYM(v, s) void* v##_; cudaGetSymbolAddress(&v##_, s);
    SYM(pe, g_pe) SYM(bias, g_bias) SYM(xh, g_xh) SYM(xl, g_xl)
    SYM(wh, g_wh) SYM(wl, g_wl)
    SYM(qh, g_qh) SYM(ql, g_ql) SYM(kh, g_kh) SYM(kl, g_kl)
    SYM(vt, g_vt) SYM(sc, g_sc) SYM(sph, g_ph)
#undef SYM

    // 0: prep
    prep_kernel<<<4096 + 3072 + 6, 256>>>(Wq, Wk, Wv, bq, bk, bv,
        (float*)pe_, (float*)bias_, (__half*)wh_, (__half*)wl_);
    // 1: conv_x
    conv_x_kernel<<<(NROWS * H_DIM + 255) / 256, 256>>>(in_e, (float*)pe_,
        (__half*)xh_, (__half*)xl_);

    GemmParams p;
    p.qh = (__half*)qh_; p.ql = (__half*)ql_;
    p.kh = (__half*)kh_; p.kl = (__half*)kl_;
    p.vt = (__half*)vt_;

    // 2: fused QKV: [16384,1536] = x @ Wstack^T + b
    p.Ah = (const __half*)xh_; p.Al = (const __half*)xl_;
    p.Bh = (const __half*)wh_; p.Bl = (const __half*)wl_;
    p.bias = (const float*)bias_;
    p.aBatch = 0; p.bBatch = 0; p.aRow = H_DIM; p.bRow = H_DIM; p.K = H_DIM;
    p.outF = nullptr; p.oBatch = 0; p.oRow = 0;
    dim3 gqkv(NSTACK / 128, NROWS / 128, 1);
    tc_gemm<3,0><<<gqkv, 128, SMEM3>>>(p);

    // 3: scores = q @ k^T per batch (fp32 out)
    p.Ah = (const __half*)qh_; p.Al = (const __half*)ql_;
    p.Bh = (const __half*)kh_; p.Bl = (const __half*)kl_;
    p.aBatch = (long long)S_DIM * H_DIM; p.bBatch = (long long)S_DIM * H_DIM;
    p.aRow = H_DIM; p.bRow = H_DIM; p.K = H_DIM;
    p.outF = (float*)sc_;
    p.oBatch = (long long)S_DIM * S_DIM; p.oRow = S_DIM;
    dim3 gs(S_DIM / 128, S_DIM / 128, B_DIM);
    tc_gemm<3,2><<<gs, 128, SMEM3>>>(p);

    // 4: softmax -> fp16 probs
    softmax_kernel<<<B_DIM * S_DIM, 256>>>((const float*)sc_, (__half*)sph_);

    // 5: out = probs @ v (single product, NT with B = vT) — ncu -s 5 target
    p.Ah = (const __half*)sph_; p.Al = nullptr;
    p.Bh = (const __half*)vt_;  p.Bl = nullptr;
    p.aBatch = (long long)S_DIM * S_DIM; p.bBatch = S_DIM;
    p.aRow = S_DIM; p.bRow = NROWS; p.K = S_DIM;
    p.outF = out;
    p.oBatch = (long long)S_DIM * H_DIM; p.oRow = H_DIM;
    dim3 go(H_DIM / 128, S_DIM / 128, B_DIM);
    tc_gemm<1,2><<<go, 128, SMEM1>>>(p);
}

// round 11
// speedup vs baseline: 1.1868x; 1.1868x over previous
#include <cuda_runtime.h>
#include <cuda_fp16.h>
#include <cstdint>
#include <math.h>

#define B_DIM 8
#define S_DIM 2048
#define H_DIM 512
#define NROWS (B_DIM * S_DIM)          // 16384
#define NSTACK (3 * H_DIM)             // 1536

// ---------------- scratch (device globals; no allocations allowed) ----------
__device__ float g_pe[S_DIM * H_DIM];
__device__ float g_bias[NSTACK];
__device__ __half g_xh[NROWS * H_DIM], g_xl[NROWS * H_DIM];
__device__ __half g_wh[NSTACK * H_DIM], g_wl[NSTACK * H_DIM];   // stacked Wq,Wk,Wv
__device__ __half g_qh[NROWS * H_DIM], g_ql[NROWS * H_DIM];
__device__ __half g_kh[NROWS * H_DIM], g_kl[NROWS * H_DIM];
__device__ __half g_vt[H_DIM * NROWS];                          // v transposed, fp16
__device__ float g_sc[(long long)B_DIM * S_DIM * S_DIM];        // 134 MB
__device__ __half g_ph[(long long)B_DIM * S_DIM * S_DIM];       // probs fp16

// ---------------- helpers ----------------------------------------------
__device__ __forceinline__ uint32_t smem_u32(const void* p) {
    uint32_t a;
    asm("{ .reg .u64 t; cvta.to.shared.u64 t, %1; cvt.u32.u64 %0, t; }" : "=r"(a) : "l"(p));
    return a;
}
__device__ __forceinline__ void cp16(uint32_t dst, const void* src) {
    asm volatile("cp.async.cg.shared.global [%0], [%1], 16;"
                 :: "r"(dst), "l"(__cvta_generic_to_global(src)));
}
#define CP_COMMIT() asm volatile("cp.async.commit_group;" ::: "memory")
#define CP_WAIT_0() asm volatile("cp.async.wait_group 0;" ::: "memory")

__device__ __forceinline__ void ldsm4(uint32_t& r0, uint32_t& r1, uint32_t& r2, uint32_t& r3,
                                      uint32_t addr) {
    asm volatile("ldmatrix.sync.aligned.m8n8.x4.shared.b16 {%0,%1,%2,%3}, [%4];"
                 : "=r"(r0), "=r"(r1), "=r"(r2), "=r"(r3) : "r"(addr));
}
__device__ __forceinline__ void mma16816(float* c, const uint32_t* a, const uint32_t* b) {
    asm volatile(
        "mma.sync.aligned.m16n8k16.row.col.f32.f16.f16.f32 "
        "{%0,%1,%2,%3}, {%4,%5,%6,%7}, {%8,%9}, {%0,%1,%2,%3};"
        : "+f"(c[0]), "+f"(c[1]), "+f"(c[2]), "+f"(c[3])
        : "r"(a[0]), "r"(a[1]), "r"(a[2]), "r"(a[3]), "r"(b[0]), "r"(b[1]));
}
__device__ __forceinline__ void split2h(float v, unsigned short& h, unsigned short& l) {
    __half hh = __float2half_rn(v);
    __half ll = __float2half_rn(v - __half2float(hh));
    h = __half_as_ushort(hh);
    l = __half_as_ushort(ll);
}

// ---------------- split-fp16 HMMA GEMM: C = A * B^T -------------------------
// Block tile 128x128, BK=32, 256 threads (4x2 warps), warp tile 32x64.
// SMEM rows: pitch 80B (64B data + 16B pad) -> conflict-free ldsm.
// Single-sync double buffer: [load c+1][compute c][wait+sync].
struct GemmParams {
    const __half *Ah, *Al, *Bh, *Bl;
    const float* bias;
    long long aBatch, bBatch;
    int aRow, bRow, K;
    __half *qh, *ql, *kh, *kl, *vt;    // MODE 0 outputs
    float* outF;                        // MODE 2 output
    long long oBatch;
    int oRow;
};

#define PITCH   80
#define TILE_SZ (128 * PITCH)           // 10240

template<int NPROD, int MODE>   // MODE: 0 = fused QKV epilogue, 2 = fp32 out
__global__ __launch_bounds__(256, 2) void tc_gemm(GemmParams p) {
    constexpr int NT = (NPROD == 3) ? 4 : 2;
    constexpr int STAGE = NT * TILE_SZ;
    extern __shared__ char smem[];
    uint32_t sbase = smem_u32(smem);

    const int tid = threadIdx.x;
    const int wid = tid >> 5, lane = tid & 31;
    const int wm = wid & 3, wn = wid >> 2;          // warp tile (wm*32, wn*64)

    const int bm = blockIdx.y * 128, bn = blockIdx.x * 128, z = blockIdx.z;
    const __half* Ah = p.Ah + (long long)z * p.aBatch;
    const __half* Al = p.Al + (long long)z * p.aBatch;
    const __half* Bh = p.Bh + (long long)z * p.bBatch;
    const __half* Bl = p.Bl + (long long)z * p.bBatch;
    const int aRow = p.aRow, bRow = p.bRow;

    const int nc = p.K >> 5;

    auto load_chunk = [&](int c, int s) {
        uint32_t st = sbase + s * STAGE;
        long long kofs = (long long)c * 32;
#pragma unroll
        for (int t = 0; t < NT; t++) {
            const __half* src;
            int rbase, rstride;
            if (NPROD == 3) {
                if (t == 0)      { src = Ah; rbase = bm; rstride = aRow; }
                else if (t == 1) { src = Al; rbase = bm; rstride = aRow; }
                else if (t == 2) { src = Bh; rbase = bn; rstride = bRow; }
                else             { src = Bl; rbase = bn; rstride = bRow; }
            } else {
                if (t == 0)      { src = Ah; rbase = bm; rstride = aRow; }
                else             { src = Bh; rbase = bn; rstride = bRow; }
            }
            uint32_t tb = st + t * TILE_SZ;
#pragma unroll
            for (int it = 0; it < 2; it++) {
                int u = tid + it * 256;            // 512 units per tile
                int row = u >> 2, ch = u & 3;
                cp16(tb + row * PITCH + ch * 16,
                     src + (long long)(rbase + row) * rstride + kofs + ch * 8);
            }
        }
        CP_COMMIT();
    };

    float acc[2][8][4];
#pragma unroll
    for (int i = 0; i < 2; i++)
#pragma unroll
        for (int j = 0; j < 8; j++)
#pragma unroll
            for (int r = 0; r < 4; r++) acc[i][j][r] = 0.f;

    // prologue: stage 0 ready before loop
    load_chunk(0, 0);
    CP_WAIT_0();
    __syncthreads();

    for (int c = 0; c < nc; c++) {
        int s = c & 1;
        if (c + 1 < nc) load_chunk(c + 1, s ^ 1);

        uint32_t st = sbase + s * STAGE;
        uint32_t aHB = st, aLB = st + TILE_SZ;
        uint32_t bHB = st + (NT - 2) * TILE_SZ;
        uint32_t bLB = st + (NT - 1) * TILE_SZ;
        if (NPROD == 1) bHB = st + TILE_SZ;

#pragma unroll
        for (int ks = 0; ks < 2; ks++) {
            const int chcol = (ks * 2 + (lane >> 4)) * 16;
            uint32_t ah[2][4], al[2][4];
#pragma unroll
            for (int t = 0; t < 2; t++) {
                int row = wm * 32 + t * 16 + (lane & 15);
                uint32_t off = row * PITCH + chcol;
                ldsm4(ah[t][0], ah[t][1], ah[t][2], ah[t][3], aHB + off);
                if (NPROD == 3)
                    ldsm4(al[t][0], al[t][1], al[t][2], al[t][3], aLB + off);
            }
#pragma unroll
            for (int jh = 0; jh < 2; jh++) {
                uint32_t bh[4][2], bl[4][2];
#pragma unroll
                for (int jj = 0; jj < 2; jj++) {
                    int row = wn * 64 + (jh * 2 + jj) * 16 + (lane & 15);
                    uint32_t off = row * PITCH + chcol;
                    uint32_t r0, r1, r2, r3;
                    ldsm4(r0, r1, r2, r3, bHB + off);
                    bh[jj * 2][0] = r0; bh[jj * 2][1] = r2;
                    bh[jj * 2 + 1][0] = r1; bh[jj * 2 + 1][1] = r3;
                    if (NPROD == 3) {
                        ldsm4(r0, r1, r2, r3, bLB + off);
                        bl[jj * 2][0] = r0; bl[jj * 2][1] = r2;
                        bl[jj * 2 + 1][0] = r1; bl[jj * 2 + 1][1] = r3;
                    }
                }
#pragma unroll
                for (int i = 0; i < 2; i++)
#pragma unroll
                    for (int j4 = 0; j4 < 4; j4++)
                        mma16816(acc[i][jh * 4 + j4], ah[i], bh[j4]);
                if (NPROD == 3) {
#pragma unroll
                    for (int i = 0; i < 2; i++)
#pragma unroll
                        for (int j4 = 0; j4 < 4; j4++)
                            mma16816(acc[i][jh * 4 + j4], ah[i], bl[j4]);
#pragma unroll
                    for (int i = 0; i < 2; i++)
#pragma unroll
                        for (int j4 = 0; j4 < 4; j4++)
                            mma16816(acc[i][jh * 4 + j4], al[i], bh[j4]);
                }
            }
        }
        CP_WAIT_0();
        __syncthreads();
    }

    // --------- epilogue ---------
    if (MODE == 2) {
        float* o0 = p.outF + (long long)z * p.oBatch;
        const int mB = bm + wm * 32 + (lane >> 2);
        const int nB = bn + wn * 64 + (lane & 3) * 2;
#pragma unroll
        for (int i = 0; i < 2; i++)
#pragma unroll
            for (int j = 0; j < 8; j++) {
                int m = mB + i * 16, n = nB + j * 8;
                *(float2*)(o0 + (long long)m * p.oRow + n)       = make_float2(acc[i][j][0], acc[i][j][1]);
                *(float2*)(o0 + (long long)(m + 8) * p.oRow + n) = make_float2(acc[i][j][2], acc[i][j][3]);
            }
    } else {
        const int sel = bn >> 9;                    // 0=Q 1=K 2=V
        if (sel < 2) {
            __half* o0 = sel ? p.kh : p.qh;
            __half* o1 = sel ? p.kl : p.ql;
            const int mB = bm + wm * 32 + (lane >> 2);
            const int nW = wn * 64 + (lane & 3) * 2;
#pragma unroll
            for (int i = 0; i < 2; i++)
#pragma unroll
                for (int j = 0; j < 8; j++) {
                    int m = mB + i * 16;
                    int nl = (bn & 511) + nW + j * 8;
                    float b0 = p.bias[bn + nW + j * 8], b1 = p.bias[bn + nW + j * 8 + 1];
                    unsigned short h0, l0, h1, l1;
#pragma unroll
                    for (int hf = 0; hf < 2; hf++) {
                        int mm = m + hf * 8;
                        split2h(acc[i][j][hf * 2 + 0] + b0, h0, l0);
                        split2h(acc[i][j][hf * 2 + 1] + b1, h1, l1);
                        long long a = (long long)mm * H_DIM + nl;
                        *(ushort2*)(o0 + a) = make_ushort2(h0, h1);
                        *(ushort2*)(o1 + a) = make_ushort2(l0, l1);
                    }
                }
        } else {
            // V: transposed fp16 out via smem staging [128][129] u32
            uint32_t* stg = (uint32_t*)smem;
            __syncthreads();
#pragma unroll
            for (int i = 0; i < 2; i++)
#pragma unroll
                for (int j = 0; j < 8; j++)
#pragma unroll
                    for (int r = 0; r < 4; r++) {
                        int ml = wm * 32 + i * 16 + (r >> 1) * 8 + (lane >> 2);
                        int nl = wn * 64 + j * 8 + (lane & 3) * 2 + (r & 1);
                        float v = acc[i][j][r] + p.bias[bn + nl];
                        stg[ml * 129 + nl] = (uint32_t)__half_as_ushort(__float2half_rn(v));
                    }
            __syncthreads();
            int col = tid >> 1, rch = (tid & 1) * 64;
            int n = (bn & 511) + col;
            long long base = (long long)n * NROWS + bm + rch;
#pragma unroll
            for (int r = 0; r < 64; r += 2) {
                uint32_t w0 = stg[(rch + r) * 129 + col];
                uint32_t w1 = stg[(rch + r + 1) * 129 + col];
                *(ushort2*)(p.vt + base + r) =
                    make_ushort2((unsigned short)w0, (unsigned short)w1);
            }
        }
    }
}

// ---------------- prep: pe table (fp32, matching reference) + weights -------
__global__ void prep_kernel(const float* __restrict__ Wq, const float* __restrict__ Wk,
                            const float* __restrict__ Wv,
                            const float* __restrict__ bq, const float* __restrict__ bk,
                            const float* __restrict__ bv,
                            float* __restrict__ pe, float* __restrict__ bias,
                            __half* __restrict__ wh, __half* __restrict__ wl) {
    int b = blockIdx.x, t = threadIdx.x;
    if (b < 4096) {                                    // pe: 1M elements, pure fp32
        int idx = b * 256 + t;
        int h = idx & (H_DIM - 1);
        int s = idx >> 9;
        int j = (h < H_DIM / 2) ? h : h - H_DIM / 2;
        // reference computes in float32: div = exp(2j * (-ln(1e4)/512))
        float d   = expf((float)(2 * j) * (-9.210340371976184f / 512.0f));
        float ang = (float)s * d;
        pe[idx] = (h < H_DIM / 2) ? sinf(ang) : cosf(ang);
    } else if (b < 4096 + 3072) {                      // stacked weights 1536x512
        int idx = (b - 4096) * 256 + t;
        int w = idx >> 18;
        int off = idx & 262143;
        const float* W = (w == 0) ? Wq : (w == 1) ? Wk : Wv;
        unsigned short h, l;
        split2h(W[off], h, l);
        wh[idx] = __ushort_as_half(h);
        wl[idx] = __ushort_as_half(l);
    } else {                                           // stacked bias 1536
        int i = (b - 4096 - 3072) * 256 + t;
        if (i < NSTACK)
            bias[i] = (i < 512) ? bq[i] : (i < 1024) ? bk[i - 512] : bv[i - 1024];
    }
}

__global__ void conv_x_kernel(const float* __restrict__ in, const float* __restrict__ pe,
                              __half* __restrict__ xh, __half* __restrict__ xl) {
    int i = blockIdx.x * blockDim.x + threadIdx.x;
    if (i >= NROWS * H_DIM) return;
    float v = in[i] + pe[i & (S_DIM * H_DIM - 1)];
    unsigned short h, l;
    split2h(v, h, l);
    xh[i] = __ushort_as_half(h);
    xl[i] = __ushort_as_half(l);
}

// ---------------- softmax: fp32 in, fp16 out, __expf ------------------------
__global__ __launch_bounds__(256) void softmax_kernel(const float* __restrict__ sc,
                                                      __half* __restrict__ ph) {
    const float* row = sc + (long long)blockIdx.x * S_DIM;
    long long obase = (long long)blockIdx.x * S_DIM + threadIdx.x * 8;
    int tid = threadIdx.x;
    __shared__ float red[256];

    float4 a = *(const float4*)(row + tid * 8);
    float4 b = *(const float4*)(row + tid * 8 + 4);
    float m = fmaxf(fmaxf(fmaxf(a.x, a.y), fmaxf(a.z, a.w)),
                    fmaxf(fmaxf(b.x, b.y), fmaxf(b.z, b.w)));
    red[tid] = m; __syncthreads();
    for (int s = 128; s > 0; s >>= 1) {
        if (tid < s) red[tid] = fmaxf(red[tid], red[tid + s]);
        __syncthreads();
    }
    m = red[0]; __syncthreads();

    float e[8];
    e[0] = __expf(a.x - m); e[1] = __expf(a.y - m); e[2] = __expf(a.z - m); e[3] = __expf(a.w - m);
    e[4] = __expf(b.x - m); e[5] = __expf(b.y - m); e[6] = __expf(b.z - m); e[7] = __expf(b.w - m);
    float sum = 0.f;
#pragma unroll
    for (int i = 0; i < 8; i++) sum += e[i];
    red[tid] = sum; __syncthreads();
    for (int s = 128; s > 0; s >>= 1) {
        if (tid < s) red[tid] += red[tid + s];
        __syncthreads();
    }
    float inv = 1.f / red[0];
#pragma unroll
    for (int i = 0; i < 4; i++) {
        __half2 w2 = __floats2half2_rn(e[i * 2] * inv, e[i * 2 + 1] * inv);
        *(__half2*)(ph + obase + i * 2) = w2;
    }
}

// ---------------- launch ----------------------------------------------------
extern "C" void kernel_launch(void* const* d_in, const int* in_sizes, int n_in,
                              void* d_out, int out_size) {
    const float* in_e = (const float*)d_in[0];
    const float* Wq   = (const float*)d_in[1];
    const float* bq   = (const float*)d_in[2];
    const float* Wk   = (const float*)d_in[3];
    const float* bk   = (const float*)d_in[4];
    const float* Wv   = (const float*)d_in[5];
    const float* bv   = (const float*)d_in[6];
    float* out = (float*)d_out;

    const int SMEM3 = 2 * 4 * TILE_SZ;   // 81920
    const int SMEM1 = 2 * 2 * TILE_SZ;   // 40960
    cudaFuncSetAttribute(tc_gemm<3,0>, cudaFuncAttributeMaxDynamicSharedMemorySize, SMEM3);
    cudaFuncSetAttribute(tc_gemm<3,2>, cudaFuncAttributeMaxDynamicSharedMemorySize, SMEM3);
    cudaFuncSetAttribute(tc_gemm<1,2>, cudaFuncAttributeMaxDynamicSharedMemorySize, SMEM1);

#define SYM(v, s) void* v##_; cudaGetSymbolAddress(&v##_, s);
    SYM(pe, g_pe) SYM(bias, g_bias) SYM(xh, g_xh) SYM(xl, g_xl)
    SYM(wh, g_wh) SYM(wl, g_wl)
    SYM(qh, g_qh) SYM(ql, g_ql) SYM(kh, g_kh) SYM(kl, g_kl)
    SYM(vt, g_vt) SYM(sc, g_sc) SYM(sph, g_ph)
#undef SYM

    // 0: prep (fp32 pe + stacked weights + stacked bias)
    prep_kernel<<<4096 + 3072 + 6, 256>>>(Wq, Wk, Wv, bq, bk, bv,
        (float*)pe_, (float*)bias_, (__half*)wh_, (__half*)wl_);
    // 1: conv_x
    conv_x_kernel<<<(NROWS * H_DIM + 255) / 256, 256>>>(in_e, (float*)pe_,
        (__half*)xh_, (__half*)xl_);

    GemmParams p;
    p.qh = (__half*)qh_; p.ql = (__half*)ql_;
    p.kh = (__half*)kh_; p.kl = (__half*)kl_;
    p.vt = (__half*)vt_;

    // 2: fused QKV: [16384,1536] = x @ Wstack^T + b
    p.Ah = (const __half*)xh_; p.Al = (const __half*)xl_;
    p.Bh = (const __half*)wh_; p.Bl = (const __half*)wl_;
    p.bias = (const float*)bias_;
    p.aBatch = 0; p.bBatch = 0; p.aRow = H_DIM; p.bRow = H_DIM; p.K = H_DIM;
    p.outF = nullptr; p.oBatch = 0; p.oRow = 0;
    dim3 gqkv(NSTACK / 128, NROWS / 128, 1);
    tc_gemm<3,0><<<gqkv, 256, SMEM3>>>(p);

    // 3: scores = q @ k^T per batch (fp32 out)
    p.Ah = (const __half*)qh_; p.Al = (const __half*)ql_;
    p.Bh = (const __half*)kh_; p.Bl = (const __half*)kl_;
    p.aBatch = (long long)S_DIM * H_DIM; p.bBatch = (long long)S_DIM * H_DIM;
    p.aRow = H_DIM; p.bRow = H_DIM; p.K = H_DIM;
    p.outF = (float*)sc_;
    p.oBatch = (long long)S_DIM * S_DIM; p.oRow = S_DIM;
    dim3 gs(S_DIM / 128, S_DIM / 128, B_DIM);
    tc_gemm<3,2><<<gs, 256, SMEM3>>>(p);

    // 4: softmax -> fp16 probs
    softmax_kernel<<<B_DIM * S_DIM, 256>>>((const float*)sc_, (__half*)sph_);

    // 5: out = probs @ v (single product, NT with B = vT) — ncu -s 5 target
    p.Ah = (const __half*)sph_; p.Al = nullptr;
    p.Bh = (const __half*)vt_;  p.Bl = nullptr;
    p.aBatch = (long long)S_DIM * S_DIM; p.bBatch = S_DIM;
    p.aRow = S_DIM; p.bRow = NROWS; p.K = S_DIM;
    p.outF = out;
    p.oBatch = (long long)S_DIM * H_DIM; p.oRow = H_DIM;
    dim3 go(H_DIM / 128, S_DIM / 128, B_DIM);
    tc_gemm<1,2><<<go, 256, SMEM1>>>(p);
}

// round 12
// speedup vs baseline: 1.1933x; 1.0055x over previous
#include <cuda_runtime.h>
#include <cuda_fp16.h>
#include <cstdint>
#include <math.h>

#define B_DIM 8
#define S_DIM 2048
#define H_DIM 512
#define NROWS (B_DIM * S_DIM)          // 16384
#define NSTACK (3 * H_DIM)             // 1536

// ---------------- scratch (device globals; no allocations allowed) ----------
__device__ float g_pe[S_DIM * H_DIM];
__device__ float g_bias[NSTACK];
__device__ __half g_xh[NROWS * H_DIM], g_xl[NROWS * H_DIM];
__device__ __half g_wh[NSTACK * H_DIM], g_wl[NSTACK * H_DIM];   // stacked Wq,Wk,Wv
__device__ __half g_qh[NROWS * H_DIM], g_ql[NROWS * H_DIM];
__device__ __half g_kh[NROWS * H_DIM], g_kl[NROWS * H_DIM];
__device__ __half g_vt[H_DIM * NROWS];                          // v transposed, fp16
__device__ float g_sc[(long long)B_DIM * S_DIM * S_DIM];        // 134 MB
__device__ __half g_ph[(long long)B_DIM * S_DIM * S_DIM];       // probs fp16

// ---------------- helpers ----------------------------------------------
__device__ __forceinline__ uint32_t smem_u32(const void* p) {
    uint32_t a;
    asm("{ .reg .u64 t; cvta.to.shared.u64 t, %1; cvt.u32.u64 %0, t; }" : "=r"(a) : "l"(p));
    return a;
}
__device__ __forceinline__ void cp16(uint32_t dst, const void* src) {
    asm volatile("cp.async.cg.shared.global [%0], [%1], 16;"
                 :: "r"(dst), "l"(__cvta_generic_to_global(src)));
}
#define CP_COMMIT() asm volatile("cp.async.commit_group;" ::: "memory")
#define CP_WAIT_0() asm volatile("cp.async.wait_group 0;" ::: "memory")

__device__ __forceinline__ void ldsm4(uint32_t& r0, uint32_t& r1, uint32_t& r2, uint32_t& r3,
                                      uint32_t addr) {
    asm volatile("ldmatrix.sync.aligned.m8n8.x4.shared.b16 {%0,%1,%2,%3}, [%4];"
                 : "=r"(r0), "=r"(r1), "=r"(r2), "=r"(r3) : "r"(addr));
}
__device__ __forceinline__ void mma16816(float* c, const uint32_t* a, const uint32_t* b) {
    asm volatile(
        "mma.sync.aligned.m16n8k16.row.col.f32.f16.f16.f32 "
        "{%0,%1,%2,%3}, {%4,%5,%6,%7}, {%8,%9}, {%0,%1,%2,%3};"
        : "+f"(c[0]), "+f"(c[1]), "+f"(c[2]), "+f"(c[3])
        : "r"(a[0]), "r"(a[1]), "r"(a[2]), "r"(a[3]), "r"(b[0]), "r"(b[1]));
}
__device__ __forceinline__ void split2h(float v, unsigned short& h, unsigned short& l) {
    __half hh = __float2half_rn(v);
    __half ll = __float2half_rn(v - __half2float(hh));
    h = __half_as_ushort(hh);
    l = __half_as_ushort(ll);
}

// ---------------- split-fp16 HMMA GEMM: C = A * B^T -------------------------
// Block tile 128x128, BK=32, 256 threads (4x2 warps), warp tile 32x64.
// SMEM rows: pitch 80B (64B data + 16B pad) -> conflict-free ldsm.
// Inner loop: product-major over FULL j range -> acc reuse distance 16 MMAs.
struct GemmParams {
    const __half *Ah, *Al, *Bh, *Bl;
    const float* bias;
    long long aBatch, bBatch;
    int aRow, bRow, K;
    __half *qh, *ql, *kh, *kl, *vt;    // MODE 0 outputs
    float* outF;                        // MODE 2 output
    long long oBatch;
    int oRow;
};

#define PITCH   80
#define TILE_SZ (128 * PITCH)           // 10240

template<int NPROD, int MODE>   // MODE: 0 = fused QKV epilogue, 2 = fp32 out
__global__ __launch_bounds__(256, 2) void tc_gemm(GemmParams p) {
    constexpr int NT = (NPROD == 3) ? 4 : 2;
    constexpr int STAGE = NT * TILE_SZ;
    extern __shared__ char smem[];
    uint32_t sbase = smem_u32(smem);

    const int tid = threadIdx.x;
    const int wid = tid >> 5, lane = tid & 31;
    const int wm = wid & 3, wn = wid >> 2;          // warp tile (wm*32, wn*64)

    const int bm = blockIdx.y * 128, bn = blockIdx.x * 128, z = blockIdx.z;
    const __half* Ah = p.Ah + (long long)z * p.aBatch;
    const __half* Al = p.Al + (long long)z * p.aBatch;
    const __half* Bh = p.Bh + (long long)z * p.bBatch;
    const __half* Bl = p.Bl + (long long)z * p.bBatch;
    const int aRow = p.aRow, bRow = p.bRow;

    const int nc = p.K >> 5;

    auto load_chunk = [&](int c, int s) {
        uint32_t st = sbase + s * STAGE;
        long long kofs = (long long)c * 32;
#pragma unroll
        for (int t = 0; t < NT; t++) {
            const __half* src;
            int rbase, rstride;
            if (NPROD == 3) {
                if (t == 0)      { src = Ah; rbase = bm; rstride = aRow; }
                else if (t == 1) { src = Al; rbase = bm; rstride = aRow; }
                else if (t == 2) { src = Bh; rbase = bn; rstride = bRow; }
                else             { src = Bl; rbase = bn; rstride = bRow; }
            } else {
                if (t == 0)      { src = Ah; rbase = bm; rstride = aRow; }
                else             { src = Bh; rbase = bn; rstride = bRow; }
            }
            uint32_t tb = st + t * TILE_SZ;
#pragma unroll
            for (int it = 0; it < 2; it++) {
                int u = tid + it * 256;            // 512 units per tile
                int row = u >> 2, ch = u & 3;
                cp16(tb + row * PITCH + ch * 16,
                     src + (long long)(rbase + row) * rstride + kofs + ch * 8);
            }
        }
        CP_COMMIT();
    };

    float acc[2][8][4];
#pragma unroll
    for (int i = 0; i < 2; i++)
#pragma unroll
        for (int j = 0; j < 8; j++)
#pragma unroll
            for (int r = 0; r < 4; r++) acc[i][j][r] = 0.f;

    // prologue: stage 0 ready before loop
    load_chunk(0, 0);
    CP_WAIT_0();
    __syncthreads();

    for (int c = 0; c < nc; c++) {
        int s = c & 1;
        if (c + 1 < nc) load_chunk(c + 1, s ^ 1);

        uint32_t st = sbase + s * STAGE;
        uint32_t aHB = st, aLB = st + TILE_SZ;
        uint32_t bHB = st + (NT - 2) * TILE_SZ;
        uint32_t bLB = st + (NT - 1) * TILE_SZ;
        if (NPROD == 1) bHB = st + TILE_SZ;

#pragma unroll
        for (int ks = 0; ks < 2; ks++) {
            const int chcol = (ks * 2 + (lane >> 4)) * 16;
            uint32_t ah[2][4], al[2][4];
#pragma unroll
            for (int t = 0; t < 2; t++) {
                int row = wm * 32 + t * 16 + (lane & 15);
                uint32_t off = row * PITCH + chcol;
                ldsm4(ah[t][0], ah[t][1], ah[t][2], ah[t][3], aHB + off);
                if (NPROD == 3)
                    ldsm4(al[t][0], al[t][1], al[t][2], al[t][3], aLB + off);
            }
            // full-width B fragments (8 j-tiles), hi + lo
            uint32_t bh[8][2], bl[8][2];
#pragma unroll
            for (int jj = 0; jj < 4; jj++) {
                int row = wn * 64 + jj * 16 + (lane & 15);
                uint32_t off = row * PITCH + chcol;
                uint32_t r0, r1, r2, r3;
                ldsm4(r0, r1, r2, r3, bHB + off);
                bh[jj * 2][0] = r0; bh[jj * 2][1] = r2;
                bh[jj * 2 + 1][0] = r1; bh[jj * 2 + 1][1] = r3;
                if (NPROD == 3) {
                    ldsm4(r0, r1, r2, r3, bLB + off);
                    bl[jj * 2][0] = r0; bl[jj * 2][1] = r2;
                    bl[jj * 2 + 1][0] = r1; bl[jj * 2 + 1][1] = r3;
                }
            }
            // product-major sweeps: same-acc reuse distance = 16 MMAs
#pragma unroll
            for (int i = 0; i < 2; i++)
#pragma unroll
                for (int j = 0; j < 8; j++)
                    mma16816(acc[i][j], ah[i], bh[j]);
            if (NPROD == 3) {
#pragma unroll
                for (int i = 0; i < 2; i++)
#pragma unroll
                    for (int j = 0; j < 8; j++)
                        mma16816(acc[i][j], ah[i], bl[j]);
#pragma unroll
                for (int i = 0; i < 2; i++)
#pragma unroll
                    for (int j = 0; j < 8; j++)
                        mma16816(acc[i][j], al[i], bh[j]);
            }
        }
        CP_WAIT_0();
        __syncthreads();
    }

    // --------- epilogue ---------
    if (MODE == 2) {
        float* o0 = p.outF + (long long)z * p.oBatch;
        const int mB = bm + wm * 32 + (lane >> 2);
        const int nB = bn + wn * 64 + (lane & 3) * 2;
#pragma unroll
        for (int i = 0; i < 2; i++)
#pragma unroll
            for (int j = 0; j < 8; j++) {
                int m = mB + i * 16, n = nB + j * 8;
                *(float2*)(o0 + (long long)m * p.oRow + n)       = make_float2(acc[i][j][0], acc[i][j][1]);
                *(float2*)(o0 + (long long)(m + 8) * p.oRow + n) = make_float2(acc[i][j][2], acc[i][j][3]);
            }
    } else {
        const int sel = bn >> 9;                    // 0=Q 1=K 2=V
        if (sel < 2) {
            __half* o0 = sel ? p.kh : p.qh;
            __half* o1 = sel ? p.kl : p.ql;
            const int mB = bm + wm * 32 + (lane >> 2);
            const int nW = wn * 64 + (lane & 3) * 2;
#pragma unroll
            for (int i = 0; i < 2; i++)
#pragma unroll
                for (int j = 0; j < 8; j++) {
                    int m = mB + i * 16;
                    int nl = (bn & 511) + nW + j * 8;
                    float b0 = p.bias[bn + nW + j * 8], b1 = p.bias[bn + nW + j * 8 + 1];
                    unsigned short h0, l0, h1, l1;
#pragma unroll
                    for (int hf = 0; hf < 2; hf++) {
                        int mm = m + hf * 8;
                        split2h(acc[i][j][hf * 2 + 0] + b0, h0, l0);
                        split2h(acc[i][j][hf * 2 + 1] + b1, h1, l1);
                        long long a = (long long)mm * H_DIM + nl;
                        *(ushort2*)(o0 + a) = make_ushort2(h0, h1);
                        *(ushort2*)(o1 + a) = make_ushort2(l0, l1);
                    }
                }
        } else {
            // V: transposed fp16 out via smem staging [128][129] u32
            uint32_t* stg = (uint32_t*)smem;
            __syncthreads();
#pragma unroll
            for (int i = 0; i < 2; i++)
#pragma unroll
                for (int j = 0; j < 8; j++)
#pragma unroll
                    for (int r = 0; r < 4; r++) {
                        int ml = wm * 32 + i * 16 + (r >> 1) * 8 + (lane >> 2);
                        int nl = wn * 64 + j * 8 + (lane & 3) * 2 + (r & 1);
                        float v = acc[i][j][r] + p.bias[bn + nl];
                        stg[ml * 129 + nl] = (uint32_t)__half_as_ushort(__float2half_rn(v));
                    }
            __syncthreads();
            int col = tid >> 1, rch = (tid & 1) * 64;
            int n = (bn & 511) + col;
            long long base = (long long)n * NROWS + bm + rch;
#pragma unroll
            for (int r = 0; r < 64; r += 2) {
                uint32_t w0 = stg[(rch + r) * 129 + col];
                uint32_t w1 = stg[(rch + r + 1) * 129 + col];
                *(ushort2*)(p.vt + base + r) =
                    make_ushort2((unsigned short)w0, (unsigned short)w1);
            }
        }
    }
}

// ---------------- prep: pe table (fp32, matching reference) + weights -------
__global__ void prep_kernel(const float* __restrict__ Wq, const float* __restrict__ Wk,
                            const float* __restrict__ Wv,
                            const float* __restrict__ bq, const float* __restrict__ bk,
                            const float* __restrict__ bv,
                            float* __restrict__ pe, float* __restrict__ bias,
                            __half* __restrict__ wh, __half* __restrict__ wl) {
    int b = blockIdx.x, t = threadIdx.x;
    if (b < 4096) {                                    // pe: 1M elements, pure fp32
        int idx = b * 256 + t;
        int h = idx & (H_DIM - 1);
        int s = idx >> 9;
        int j = (h < H_DIM / 2) ? h : h - H_DIM / 2;
        float d   = expf((float)(2 * j) * (-9.210340371976184f / 512.0f));
        float ang = (float)s * d;
        pe[idx] = (h < H_DIM / 2) ? sinf(ang) : cosf(ang);
    } else if (b < 4096 + 3072) {                      // stacked weights 1536x512
        int idx = (b - 4096) * 256 + t;
        int w = idx >> 18;
        int off = idx & 262143;
        const float* W = (w == 0) ? Wq : (w == 1) ? Wk : Wv;
        unsigned short h, l;
        split2h(W[off], h, l);
        wh[idx] = __ushort_as_half(h);
        wl[idx] = __ushort_as_half(l);
    } else {                                           // stacked bias 1536
        int i = (b - 4096 - 3072) * 256 + t;
        if (i < NSTACK)
            bias[i] = (i < 512) ? bq[i] : (i < 1024) ? bk[i - 512] : bv[i - 1024];
    }
}

__global__ void conv_x_kernel(const float* __restrict__ in, const float* __restrict__ pe,
                              __half* __restrict__ xh, __half* __restrict__ xl) {
    int i = blockIdx.x * blockDim.x + threadIdx.x;
    if (i >= NROWS * H_DIM) return;
    float v = in[i] + pe[i & (S_DIM * H_DIM - 1)];
    unsigned short h, l;
    split2h(v, h, l);
    xh[i] = __ushort_as_half(h);
    xl[i] = __ushort_as_half(l);
}

// ---------------- softmax: fp32 in, fp16 out, __expf ------------------------
__global__ __launch_bounds__(256) void softmax_kernel(const float* __restrict__ sc,
                                                      __half* __restrict__ ph) {
    const float* row = sc + (long long)blockIdx.x * S_DIM;
    long long obase = (long long)blockIdx.x * S_DIM + threadIdx.x * 8;
    int tid = threadIdx.x;
    __shared__ float red[256];

    float4 a = *(const float4*)(row + tid * 8);
    float4 b = *(const float4*)(row + tid * 8 + 4);
    float m = fmaxf(fmaxf(fmaxf(a.x, a.y), fmaxf(a.z, a.w)),
                    fmaxf(fmaxf(b.x, b.y), fmaxf(b.z, b.w)));
    red[tid] = m; __syncthreads();
    for (int s = 128; s > 0; s >>= 1) {
        if (tid < s) red[tid] = fmaxf(red[tid], red[tid + s]);
        __syncthreads();
    }
    m = red[0]; __syncthreads();

    float e[8];
    e[0] = __expf(a.x - m); e[1] = __expf(a.y - m); e[2] = __expf(a.z - m); e[3] = __expf(a.w - m);
    e[4] = __expf(b.x - m); e[5] = __expf(b.y - m); e[6] = __expf(b.z - m); e[7] = __expf(b.w - m);
    float sum = 0.f;
#pragma unroll
    for (int i = 0; i < 8; i++) sum += e[i];
    red[tid] = sum; __syncthreads();
    for (int s = 128; s > 0; s >>= 1) {
        if (tid < s) red[tid] += red[tid + s];
        __syncthreads();
    }
    float inv = 1.f / red[0];
#pragma unroll
    for (int i = 0; i < 4; i++) {
        __half2 w2 = __floats2half2_rn(e[i * 2] * inv, e[i * 2 + 1] * inv);
        *(__half2*)(ph + obase + i * 2) = w2;
    }
}

// ---------------- launch ----------------------------------------------------
extern "C" void kernel_launch(void* const* d_in, const int* in_sizes, int n_in,
                              void* d_out, int out_size) {
    const float* in_e = (const float*)d_in[0];
    const float* Wq   = (const float*)d_in[1];
    const float* bq   = (const float*)d_in[2];
    const float* Wk   = (const float*)d_in[3];
    const float* bk   = (const float*)d_in[4];
    const float* Wv   = (const float*)d_in[5];
    const float* bv   = (const float*)d_in[6];
    float* out = (float*)d_out;

    const int SMEM3 = 2 * 4 * TILE_SZ;   // 81920
    const int SMEM1 = 2 * 2 * TILE_SZ;   // 40960
    cudaFuncSetAttribute(tc_gemm<3,0>, cudaFuncAttributeMaxDynamicSharedMemorySize, SMEM3);
    cudaFuncSetAttribute(tc_gemm<3,2>, cudaFuncAttributeMaxDynamicSharedMemorySize, SMEM3);
    cudaFuncSetAttribute(tc_gemm<1,2>, cudaFuncAttributeMaxDynamicSharedMemorySize, SMEM1);

#define SYM(v, s) void* v##_; cudaGetSymbolAddress(&v##_, s);
    SYM(pe, g_pe) SYM(bias, g_bias) SYM(xh, g_xh) SYM(xl, g_xl)
    SYM(wh, g_wh) SYM(wl, g_wl)
    SYM(qh, g_qh) SYM(ql, g_ql) SYM(kh, g_kh) SYM(kl, g_kl)
    SYM(vt, g_vt) SYM(sc, g_sc) SYM(sph, g_ph)
#undef SYM

    // 0: prep (fp32 pe + stacked weights + stacked bias)
    prep_kernel<<<4096 + 3072 + 6, 256>>>(Wq, Wk, Wv, bq, bk, bv,
        (float*)pe_, (float*)bias_, (__half*)wh_, (__half*)wl_);
    // 1: conv_x
    conv_x_kernel<<<(NROWS * H_DIM + 255) / 256, 256>>>(in_e, (float*)pe_,
        (__half*)xh_, (__half*)xl_);

    GemmParams p;
    p.qh = (__half*)qh_; p.ql = (__half*)ql_;
    p.kh = (__half*)kh_; p.kl = (__half*)kl_;
    p.vt = (__half*)vt_;

    // 2: fused QKV: [16384,1536] = x @ Wstack^T + b
    p.Ah = (const __half*)xh_; p.Al = (const __half*)xl_;
    p.Bh = (const __half*)wh_; p.Bl = (const __half*)wl_;
    p.bias = (const float*)bias_;
    p.aBatch = 0; p.bBatch = 0; p.aRow = H_DIM; p.bRow = H_DIM; p.K = H_DIM;
    p.outF = nullptr; p.oBatch = 0; p.oRow = 0;
    dim3 gqkv(NSTACK / 128, NROWS / 128, 1);
    tc_gemm<3,0><<<gqkv, 256, SMEM3>>>(p);

    // 3: scores = q @ k^T per batch (fp32 out)
    p.Ah = (const __half*)qh_; p.Al = (const __half*)ql_;
    p.Bh = (const __half*)kh_; p.Bl = (const __half*)kl_;
    p.aBatch = (long long)S_DIM * H_DIM; p.bBatch = (long long)S_DIM * H_DIM;
    p.aRow = H_DIM; p.bRow = H_DIM; p.K = H_DIM;
    p.outF = (float*)sc_;
    p.oBatch = (long long)S_DIM * S_DIM; p.oRow = S_DIM;
    dim3 gs(S_DIM / 128, S_DIM / 128, B_DIM);
    tc_gemm<3,2><<<gs, 256, SMEM3>>>(p);

    // 4: softmax -> fp16 probs
    softmax_kernel<<<B_DIM * S_DIM, 256>>>((const float*)sc_, (__half*)sph_);

    // 5: out = probs @ v (single product, NT with B = vT) — ncu -s 5 target
    p.Ah = (const __half*)sph_; p.Al = nullptr;
    p.Bh = (const __half*)vt_;  p.Bl = nullptr;
    p.aBatch = (long long)S_DIM * S_DIM; p.bBatch = S_DIM;
    p.aRow = S_DIM; p.bRow = NROWS; p.K = S_DIM;
    p.outF = out;
    p.oBatch = (long long)S_DIM * H_DIM; p.oRow = H_DIM;
    dim3 go(H_DIM / 128, S_DIM / 128, B_DIM);
    tc_gemm<1,2><<<go, 256, SMEM1>>>(p);
}

// round 13
// speedup vs baseline: 1.3318x; 1.1161x over previous
#include <cuda_runtime.h>
#include <cuda_fp16.h>
#include <cstdint>
#include <math.h>

#define B_DIM 8
#define S_DIM 2048
#define H_DIM 512
#define NROWS (B_DIM * S_DIM)          // 16384
#define NSTACK (3 * H_DIM)             // 1536

// ---------------- scratch (device globals; no allocations allowed) ----------
__device__ float g_pe[S_DIM * H_DIM];
__device__ float g_bias[NSTACK];
__device__ __half g_xh[NROWS * H_DIM], g_xl[NROWS * H_DIM];
__device__ __half g_wh[NSTACK * H_DIM], g_wl[NSTACK * H_DIM];   // stacked Wq,Wk,Wv
__device__ __half g_qh[NROWS * H_DIM], g_ql[NROWS * H_DIM];
__device__ __half g_kh[NROWS * H_DIM], g_kl[NROWS * H_DIM];
__device__ __half g_vt[H_DIM * NROWS];                          // v transposed, fp16
__device__ float g_sc[(long long)B_DIM * S_DIM * S_DIM];        // 134 MB
__device__ __half g_ph[(long long)B_DIM * S_DIM * S_DIM];       // probs fp16

// ---------------- helpers ----------------------------------------------
__device__ __forceinline__ uint32_t smem_u32(const void* p) {
    uint32_t a;
    asm("{ .reg .u64 t; cvta.to.shared.u64 t, %1; cvt.u32.u64 %0, t; }" : "=r"(a) : "l"(p));
    return a;
}
__device__ __forceinline__ void cp16(uint32_t dst, const void* src) {
    asm volatile("cp.async.cg.shared.global [%0], [%1], 16;"
                 :: "r"(dst), "l"(__cvta_generic_to_global(src)));
}
#define CP_COMMIT() asm volatile("cp.async.commit_group;" ::: "memory")
#define CP_WAIT_0() asm volatile("cp.async.wait_group 0;" ::: "memory")

__device__ __forceinline__ void ldsm4(uint32_t& r0, uint32_t& r1, uint32_t& r2, uint32_t& r3,
                                      uint32_t addr) {
    asm volatile("ldmatrix.sync.aligned.m8n8.x4.shared.b16 {%0,%1,%2,%3}, [%4];"
                 : "=r"(r0), "=r"(r1), "=r"(r2), "=r"(r3) : "r"(addr));
}
__device__ __forceinline__ void mma16816(float* c, const uint32_t* a, const uint32_t* b) {
    asm volatile(
        "mma.sync.aligned.m16n8k16.row.col.f32.f16.f16.f32 "
        "{%0,%1,%2,%3}, {%4,%5,%6,%7}, {%8,%9}, {%0,%1,%2,%3};"
        : "+f"(c[0]), "+f"(c[1]), "+f"(c[2]), "+f"(c[3])
        : "r"(a[0]), "r"(a[1]), "r"(a[2]), "r"(a[3]), "r"(b[0]), "r"(b[1]));
}
__device__ __forceinline__ void split2h(float v, unsigned short& h, unsigned short& l) {
    __half hh = __float2half_rn(v);
    __half ll = __float2half_rn(v - __half2float(hh));
    h = __half_as_ushort(hh);
    l = __half_as_ushort(ll);
}

// ---------------- split-fp16 HMMA GEMM: C = A * B^T -------------------------
// Block tile 128x128, BK=32, 256 threads (4x2 warps), warp tile 32x64.
// SMEM rows: pitch 80B (64B data + 16B pad) -> conflict-free ldsm.
// NPROD=3: A hi/lo x B hi/lo (3 products, 4 tiles)
// NPROD=2: A hi/lo x B single (2 products, 3 tiles)
// NPROD=1: A single x B single (1 product, 2 tiles)
struct GemmParams {
    const __half *Ah, *Al, *Bh, *Bl;
    const float* bias;
    long long aBatch, bBatch;
    int aRow, bRow, K;
    __half *qh, *ql, *kh, *kl, *vt;    // MODE 0 outputs
    float* outF;                        // MODE 2 output
    long long oBatch;
    int oRow;
};

#define PITCH   80
#define TILE_SZ (128 * PITCH)           // 10240

template<int NPROD, int MODE>   // MODE: 0 = fused QKV epilogue, 2 = fp32 out
__global__ __launch_bounds__(256, 2) void tc_gemm(GemmParams p) {
    constexpr int NT = (NPROD == 3) ? 4 : (NPROD == 2) ? 3 : 2;
    constexpr int STAGE = NT * TILE_SZ;
    extern __shared__ char smem[];
    uint32_t sbase = smem_u32(smem);

    const int tid = threadIdx.x;
    const int wid = tid >> 5, lane = tid & 31;
    const int wm = wid & 3, wn = wid >> 2;          // warp tile (wm*32, wn*64)

    const int bm = blockIdx.y * 128, bn = blockIdx.x * 128, z = blockIdx.z;
    const __half* Ah = p.Ah + (long long)z * p.aBatch;
    const __half* Al = p.Al + (long long)z * p.aBatch;
    const __half* Bh = p.Bh + (long long)z * p.bBatch;
    const __half* Bl = p.Bl + (long long)z * p.bBatch;
    const int aRow = p.aRow, bRow = p.bRow;

    const int nc = p.K >> 5;

    auto load_chunk = [&](int c, int s) {
        uint32_t st = sbase + s * STAGE;
        long long kofs = (long long)c * 32;
#pragma unroll
        for (int t = 0; t < NT; t++) {
            const __half* src;
            int rbase, rstride;
            if (NPROD == 3) {
                if (t == 0)      { src = Ah; rbase = bm; rstride = aRow; }
                else if (t == 1) { src = Al; rbase = bm; rstride = aRow; }
                else if (t == 2) { src = Bh; rbase = bn; rstride = bRow; }
                else             { src = Bl; rbase = bn; rstride = bRow; }
            } else if (NPROD == 2) {
                if (t == 0)      { src = Ah; rbase = bm; rstride = aRow; }
                else if (t == 1) { src = Al; rbase = bm; rstride = aRow; }
                else             { src = Bh; rbase = bn; rstride = bRow; }
            } else {
                if (t == 0)      { src = Ah; rbase = bm; rstride = aRow; }
                else             { src = Bh; rbase = bn; rstride = bRow; }
            }
            uint32_t tb = st + t * TILE_SZ;
#pragma unroll
            for (int it = 0; it < 2; it++) {
                int u = tid + it * 256;            // 512 units per tile
                int row = u >> 2, ch = u & 3;
                cp16(tb + row * PITCH + ch * 16,
                     src + (long long)(rbase + row) * rstride + kofs + ch * 8);
            }
        }
        CP_COMMIT();
    };

    float acc[2][8][4];
#pragma unroll
    for (int i = 0; i < 2; i++)
#pragma unroll
        for (int j = 0; j < 8; j++)
#pragma unroll
            for (int r = 0; r < 4; r++) acc[i][j][r] = 0.f;

    // prologue: stage 0 ready before loop
    load_chunk(0, 0);
    CP_WAIT_0();
    __syncthreads();

    for (int c = 0; c < nc; c++) {
        int s = c & 1;
        if (c + 1 < nc) load_chunk(c + 1, s ^ 1);

        uint32_t st = sbase + s * STAGE;
        uint32_t aHB = st, aLB = st + TILE_SZ;
        uint32_t bHB = st + (NT - (NPROD == 3 ? 2 : 1)) * TILE_SZ;
        uint32_t bLB = st + (NT - 1) * TILE_SZ;      // only used for NPROD==3

#pragma unroll
        for (int ks = 0; ks < 2; ks++) {
            const int chcol = (ks * 2 + (lane >> 4)) * 16;
            uint32_t ah[2][4], al[2][4];
#pragma unroll
            for (int t = 0; t < 2; t++) {
                int row = wm * 32 + t * 16 + (lane & 15);
                uint32_t off = row * PITCH + chcol;
                ldsm4(ah[t][0], ah[t][1], ah[t][2], ah[t][3], aHB + off);
                if (NPROD >= 2)
                    ldsm4(al[t][0], al[t][1], al[t][2], al[t][3], aLB + off);
            }
            // full-width B fragments (8 j-tiles)
            uint32_t bh[8][2], bl[8][2];
#pragma unroll
            for (int jj = 0; jj < 4; jj++) {
                int row = wn * 64 + jj * 16 + (lane & 15);
                uint32_t off = row * PITCH + chcol;
                uint32_t r0, r1, r2, r3;
                ldsm4(r0, r1, r2, r3, bHB + off);
                bh[jj * 2][0] = r0; bh[jj * 2][1] = r2;
                bh[jj * 2 + 1][0] = r1; bh[jj * 2 + 1][1] = r3;
                if (NPROD == 3) {
                    ldsm4(r0, r1, r2, r3, bLB + off);
                    bl[jj * 2][0] = r0; bl[jj * 2][1] = r2;
                    bl[jj * 2 + 1][0] = r1; bl[jj * 2 + 1][1] = r3;
                }
            }
            // product-major sweeps
#pragma unroll
            for (int i = 0; i < 2; i++)
#pragma unroll
                for (int j = 0; j < 8; j++)
                    mma16816(acc[i][j], ah[i], bh[j]);
            if (NPROD >= 2) {
#pragma unroll
                for (int i = 0; i < 2; i++)
#pragma unroll
                    for (int j = 0; j < 8; j++)
                        mma16816(acc[i][j], al[i], bh[j]);
            }
            if (NPROD == 3) {
#pragma unroll
                for (int i = 0; i < 2; i++)
#pragma unroll
                    for (int j = 0; j < 8; j++)
                        mma16816(acc[i][j], ah[i], bl[j]);
            }
        }
        CP_WAIT_0();
        __syncthreads();
    }

    // --------- epilogue ---------
    if (MODE == 2) {
        float* o0 = p.outF + (long long)z * p.oBatch;
        const int mB = bm + wm * 32 + (lane >> 2);
        const int nB = bn + wn * 64 + (lane & 3) * 2;
#pragma unroll
        for (int i = 0; i < 2; i++)
#pragma unroll
            for (int j = 0; j < 8; j++) {
                int m = mB + i * 16, n = nB + j * 8;
                *(float2*)(o0 + (long long)m * p.oRow + n)       = make_float2(acc[i][j][0], acc[i][j][1]);
                *(float2*)(o0 + (long long)(m + 8) * p.oRow + n) = make_float2(acc[i][j][2], acc[i][j][3]);
            }
    } else {
        const int sel = bn >> 9;                    // 0=Q 1=K 2=V
        if (sel < 2) {
            __half* o0 = sel ? p.kh : p.qh;
            __half* o1 = sel ? p.kl : p.ql;
            const int mB = bm + wm * 32 + (lane >> 2);
            const int nW = wn * 64 + (lane & 3) * 2;
#pragma unroll
            for (int i = 0; i < 2; i++)
#pragma unroll
                for (int j = 0; j < 8; j++) {
                    int m = mB + i * 16;
                    int nl = (bn & 511) + nW + j * 8;
                    float b0 = p.bias[bn + nW + j * 8], b1 = p.bias[bn + nW + j * 8 + 1];
                    unsigned short h0, l0, h1, l1;
#pragma unroll
                    for (int hf = 0; hf < 2; hf++) {
                        int mm = m + hf * 8;
                        split2h(acc[i][j][hf * 2 + 0] + b0, h0, l0);
                        split2h(acc[i][j][hf * 2 + 1] + b1, h1, l1);
                        long long a = (long long)mm * H_DIM + nl;
                        *(ushort2*)(o0 + a) = make_ushort2(h0, h1);
                        *(ushort2*)(o1 + a) = make_ushort2(l0, l1);
                    }
                }
        } else {
            // V: transposed fp16 out via smem staging [128][129] u32
            uint32_t* stg = (uint32_t*)smem;
            __syncthreads();
#pragma unroll
            for (int i = 0; i < 2; i++)
#pragma unroll
                for (int j = 0; j < 8; j++)
#pragma unroll
                    for (int r = 0; r < 4; r++) {
                        int ml = wm * 32 + i * 16 + (r >> 1) * 8 + (lane >> 2);
                        int nl = wn * 64 + j * 8 + (lane & 3) * 2 + (r & 1);
                        float v = acc[i][j][r] + p.bias[bn + nl];
                        stg[ml * 129 + nl] = (uint32_t)__half_as_ushort(__float2half_rn(v));
                    }
            __syncthreads();
            int col = tid >> 1, rch = (tid & 1) * 64;
            int n = (bn & 511) + col;
            long long base = (long long)n * NROWS + bm + rch;
#pragma unroll
            for (int r = 0; r < 64; r += 2) {
                uint32_t w0 = stg[(rch + r) * 129 + col];
                uint32_t w1 = stg[(rch + r + 1) * 129 + col];
                *(ushort2*)(p.vt + base + r) =
                    make_ushort2((unsigned short)w0, (unsigned short)w1);
            }
        }
    }
}

// ---------------- prep: pe table (fp32, matching reference) + weights -------
__global__ void prep_kernel(const float* __restrict__ Wq, const float* __restrict__ Wk,
                            const float* __restrict__ Wv,
                            const float* __restrict__ bq, const float* __restrict__ bk,
                            const float* __restrict__ bv,
                            float* __restrict__ pe, float* __restrict__ bias,
                            __half* __restrict__ wh, __half* __restrict__ wl) {
    int b = blockIdx.x, t = threadIdx.x;
    if (b < 4096) {                                    // pe: 1M elements, pure fp32
        int idx = b * 256 + t;
        int h = idx & (H_DIM - 1);
        int s = idx >> 9;
        int j = (h < H_DIM / 2) ? h : h - H_DIM / 2;
        float d   = expf((float)(2 * j) * (-9.210340371976184f / 512.0f));
        float ang = (float)s * d;
        pe[idx] = (h < H_DIM / 2) ? sinf(ang) : cosf(ang);
    } else if (b < 4096 + 3072) {                      // stacked weights 1536x512
        int idx = (b - 4096) * 256 + t;
        int w = idx >> 18;
        int off = idx & 262143;
        const float* W = (w == 0) ? Wq : (w == 1) ? Wk : Wv;
        unsigned short h, l;
        split2h(W[off], h, l);
        wh[idx] = __ushort_as_half(h);
        wl[idx] = __ushort_as_half(l);
    } else {                                           // stacked bias 1536
        int i = (b - 4096 - 3072) * 256 + t;
        if (i < NSTACK)
            bias[i] = (i < 512) ? bq[i] : (i < 1024) ? bk[i - 512] : bv[i - 1024];
    }
}

__global__ void conv_x_kernel(const float* __restrict__ in, const float* __restrict__ pe,
                              __half* __restrict__ xh, __half* __restrict__ xl) {
    int i = blockIdx.x * blockDim.x + threadIdx.x;
    if (i >= NROWS * H_DIM) return;
    float v = in[i] + pe[i & (S_DIM * H_DIM - 1)];
    unsigned short h, l;
    split2h(v, h, l);
    xh[i] = __ushort_as_half(h);
    xl[i] = __ushort_as_half(l);
}

// ---------------- softmax: fp32 in, fp16 out, __expf ------------------------
__global__ __launch_bounds__(256) void softmax_kernel(const float* __restrict__ sc,
                                                      __half* __restrict__ ph) {
    const float* row = sc + (long long)blockIdx.x * S_DIM;
    long long obase = (long long)blockIdx.x * S_DIM + threadIdx.x * 8;
    int tid = threadIdx.x;
    __shared__ float red[256];

    float4 a = *(const float4*)(row + tid * 8);
    float4 b = *(const float4*)(row + tid * 8 + 4);
    float m = fmaxf(fmaxf(fmaxf(a.x, a.y), fmaxf(a.z, a.w)),
                    fmaxf(fmaxf(b.x, b.y), fmaxf(b.z, b.w)));
    red[tid] = m; __syncthreads();
    for (int s = 128; s > 0; s >>= 1) {
        if (tid < s) red[tid] = fmaxf(red[tid], red[tid + s]);
        __syncthreads();
    }
    m = red[0]; __syncthreads();

    float e[8];
    e[0] = __expf(a.x - m); e[1] = __expf(a.y - m); e[2] = __expf(a.z - m); e[3] = __expf(a.w - m);
    e[4] = __expf(b.x - m); e[5] = __expf(b.y - m); e[6] = __expf(b.z - m); e[7] = __expf(b.w - m);
    float sum = 0.f;
#pragma unroll
    for (int i = 0; i < 8; i++) sum += e[i];
    red[tid] = sum; __syncthreads();
    for (int s = 128; s > 0; s >>= 1) {
        if (tid < s) red[tid] += red[tid + s];
        __syncthreads();
    }
    float inv = 1.f / red[0];
#pragma unroll
    for (int i = 0; i < 4; i++) {
        __half2 w2 = __floats2half2_rn(e[i * 2] * inv, e[i * 2 + 1] * inv);
        *(__half2*)(ph + obase + i * 2) = w2;
    }
}

// ---------------- launch ----------------------------------------------------
extern "C" void kernel_launch(void* const* d_in, const int* in_sizes, int n_in,
                              void* d_out, int out_size) {
    const float* in_e = (const float*)d_in[0];
    const float* Wq   = (const float*)d_in[1];
    const float* bq   = (const float*)d_in[2];
    const float* Wk   = (const float*)d_in[3];
    const float* bk   = (const float*)d_in[4];
    const float* Wv   = (const float*)d_in[5];
    const float* bv   = (const float*)d_in[6];
    float* out = (float*)d_out;

    const int SMEM3 = 2 * 4 * TILE_SZ;   // 81920
    const int SMEM2 = 2 * 3 * TILE_SZ;   // 61440
    const int SMEM1 = 2 * 2 * TILE_SZ;   // 40960
    cudaFuncSetAttribute(tc_gemm<3,0>, cudaFuncAttributeMaxDynamicSharedMemorySize, SMEM3);
    cudaFuncSetAttribute(tc_gemm<2,2>, cudaFuncAttributeMaxDynamicSharedMemorySize, SMEM2);
    cudaFuncSetAttribute(tc_gemm<1,2>, cudaFuncAttributeMaxDynamicSharedMemorySize, SMEM1);

#define SYM(v, s) void* v##_; cudaGetSymbolAddress(&v##_, s);
    SYM(pe, g_pe) SYM(bias, g_bias) SYM(xh, g_xh) SYM(xl, g_xl)
    SYM(wh, g_wh) SYM(wl, g_wl)
    SYM(qh, g_qh) SYM(ql, g_ql) SYM(kh, g_kh) SYM(kl, g_kl)
    SYM(vt, g_vt) SYM(sc, g_sc) SYM(sph, g_ph)
#undef SYM

    // 0: prep (fp32 pe + stacked weights + stacked bias)
    prep_kernel<<<4096 + 3072 + 6, 256>>>(Wq, Wk, Wv, bq, bk, bv,
        (float*)pe_, (float*)bias_, (__half*)wh_, (__half*)wl_);
    // 1: conv_x
    conv_x_kernel<<<(NROWS * H_DIM + 255) / 256, 256>>>(in_e, (float*)pe_,
        (__half*)xh_, (__half*)xl_);

    GemmParams p;
    p.qh = (__half*)qh_; p.ql = (__half*)ql_;
    p.kh = (__half*)kh_; p.kl = (__half*)kl_;
    p.vt = (__half*)vt_;

    // 2: fused QKV: [16384,1536] = x @ Wstack^T + b (3-product)
    p.Ah = (const __half*)xh_; p.Al = (const __half*)xl_;
    p.Bh = (const __half*)wh_; p.Bl = (const __half*)wl_;
    p.bias = (const float*)bias_;
    p.aBatch = 0; p.bBatch = 0; p.aRow = H_DIM; p.bRow = H_DIM; p.K = H_DIM;
    p.outF = nullptr; p.oBatch = 0; p.oRow = 0;
    dim3 gqkv(NSTACK / 128, NROWS / 128, 1);
    tc_gemm<3,0><<<gqkv, 256, SMEM3>>>(p);

    // 3: scores = (qh+ql) @ kh^T per batch (2-product, fp32 out)
    p.Ah = (const __half*)qh_; p.Al = (const __half*)ql_;
    p.Bh = (const __half*)kh_; p.Bl = nullptr;
    p.aBatch = (long long)S_DIM * H_DIM; p.bBatch = (long long)S_DIM * H_DIM;
    p.aRow = H_DIM; p.bRow = H_DIM; p.K = H_DIM;
    p.outF = (float*)sc_;
    p.oBatch = (long long)S_DIM * S_DIM; p.oRow = S_DIM;
    dim3 gs(S_DIM / 128, S_DIM / 128, B_DIM);
    tc_gemm<2,2><<<gs, 256, SMEM2>>>(p);

    // 4: softmax -> fp16 probs
    softmax_kernel<<<B_DIM * S_DIM, 256>>>((const float*)sc_, (__half*)sph_);

    // 5: out = probs @ v (single product, NT with B = vT)
    p.Ah = (const __half*)sph_; p.Al = nullptr;
    p.Bh = (const __half*)vt_;  p.Bl = nullptr;
    p.aBatch = (long long)S_DIM * S_DIM; p.bBatch = S_DIM;
    p.aRow = S_DIM; p.bRow = NROWS; p.K = S_DIM;
    p.outF = out;
    p.oBatch = (long long)S_DIM * H_DIM; p.oRow = H_DIM;
    dim3 go(H_DIM / 128, S_DIM / 128, B_DIM);
    tc_gemm<1,2><<<go, 256, SMEM1>>>(p);
}

// round 14
// speedup vs baseline: 1.3434x; 1.0087x over previous
#include <cuda_runtime.h>
#include <cuda_fp16.h>
#include <cstdint>
#include <math.h>

#define B_DIM 8
#define S_DIM 2048
#define H_DIM 512
#define NROWS (B_DIM * S_DIM)          // 16384
#define NSTACK (3 * H_DIM)             // 1536

// ---------------- scratch (device globals; no allocations allowed) ----------
__device__ float g_pe[S_DIM * H_DIM];
__device__ float g_bias[NSTACK];
__device__ __half g_xh[NROWS * H_DIM], g_xl[NROWS * H_DIM];
__device__ __half g_wh[NSTACK * H_DIM], g_wl[NSTACK * H_DIM];   // stacked Wq,Wk,Wv
__device__ __half g_qh[NROWS * H_DIM], g_ql[NROWS * H_DIM];
__device__ __half g_kh[NROWS * H_DIM], g_kl[NROWS * H_DIM];
__device__ __half g_vt[H_DIM * NROWS];                          // v transposed, fp16
__device__ float g_sc[(long long)B_DIM * S_DIM * S_DIM];        // exp(logits), fp32
__device__ __half g_ph[(long long)B_DIM * S_DIM * S_DIM];       // probs fp16

// ---------------- helpers ----------------------------------------------
__device__ __forceinline__ uint32_t smem_u32(const void* p) {
    uint32_t a;
    asm("{ .reg .u64 t; cvta.to.shared.u64 t, %1; cvt.u32.u64 %0, t; }" : "=r"(a) : "l"(p));
    return a;
}
__device__ __forceinline__ void cp16(uint32_t dst, const void* src) {
    asm volatile("cp.async.cg.shared.global [%0], [%1], 16;"
                 :: "r"(dst), "l"(__cvta_generic_to_global(src)));
}
#define CP_COMMIT() asm volatile("cp.async.commit_group;" ::: "memory")
#define CP_WAIT_0() asm volatile("cp.async.wait_group 0;" ::: "memory")

__device__ __forceinline__ void ldsm4(uint32_t& r0, uint32_t& r1, uint32_t& r2, uint32_t& r3,
                                      uint32_t addr) {
    asm volatile("ldmatrix.sync.aligned.m8n8.x4.shared.b16 {%0,%1,%2,%3}, [%4];"
                 : "=r"(r0), "=r"(r1), "=r"(r2), "=r"(r3) : "r"(addr));
}
__device__ __forceinline__ void mma16816(float* c, const uint32_t* a, const uint32_t* b) {
    asm volatile(
        "mma.sync.aligned.m16n8k16.row.col.f32.f16.f16.f32 "
        "{%0,%1,%2,%3}, {%4,%5,%6,%7}, {%8,%9}, {%0,%1,%2,%3};"
        : "+f"(c[0]), "+f"(c[1]), "+f"(c[2]), "+f"(c[3])
        : "r"(a[0]), "r"(a[1]), "r"(a[2]), "r"(a[3]), "r"(b[0]), "r"(b[1]));
}
__device__ __forceinline__ void split2h(float v, unsigned short& h, unsigned short& l) {
    __half hh = __float2half_rn(v);
    __half ll = __float2half_rn(v - __half2float(hh));
    h = __half_as_ushort(hh);
    l = __half_as_ushort(ll);
}

// ---------------- split-fp16 HMMA GEMM: C = A * B^T -------------------------
// Block tile 128x128, BK=32, 256 threads (4x2 warps), warp tile 32x64.
// SMEM rows: pitch 80B (64B data + 16B pad) -> conflict-free ldsm.
// NPROD=3: A hi/lo x B hi/lo (3 products). NPROD=2: A hi/lo x B single.
// NPROD=1: single x single.
// MODE: 0 = fused QKV epilogue, 2 = fp32 out, 3 = exp(fp32) out (scores)
struct GemmParams {
    const __half *Ah, *Al, *Bh, *Bl;
    const float* bias;
    long long aBatch, bBatch;
    int aRow, bRow, K;
    __half *qh, *ql, *kh, *kl, *vt;    // MODE 0 outputs
    float* outF;                        // MODE 2/3 output
    long long oBatch;
    int oRow;
};

#define PITCH   80
#define TILE_SZ (128 * PITCH)           // 10240

template<int NPROD, int MODE>
__global__ __launch_bounds__(256, 2) void tc_gemm(GemmParams p) {
    constexpr int NT = (NPROD == 3) ? 4 : (NPROD == 2) ? 3 : 2;
    constexpr int STAGE = NT * TILE_SZ;
    extern __shared__ char smem[];
    uint32_t sbase = smem_u32(smem);

    const int tid = threadIdx.x;
    const int wid = tid >> 5, lane = tid & 31;
    const int wm = wid & 3, wn = wid >> 2;          // warp tile (wm*32, wn*64)

    const int bm = blockIdx.y * 128, bn = blockIdx.x * 128, z = blockIdx.z;
    const __half* Ah = p.Ah + (long long)z * p.aBatch;
    const __half* Al = p.Al + (long long)z * p.aBatch;
    const __half* Bh = p.Bh + (long long)z * p.bBatch;
    const __half* Bl = p.Bl + (long long)z * p.bBatch;
    const int aRow = p.aRow, bRow = p.bRow;

    const int nc = p.K >> 5;

    auto load_chunk = [&](int c, int s) {
        uint32_t st = sbase + s * STAGE;
        long long kofs = (long long)c * 32;
#pragma unroll
        for (int t = 0; t < NT; t++) {
            const __half* src;
            int rbase, rstride;
            if (NPROD == 3) {
                if (t == 0)      { src = Ah; rbase = bm; rstride = aRow; }
                else if (t == 1) { src = Al; rbase = bm; rstride = aRow; }
                else if (t == 2) { src = Bh; rbase = bn; rstride = bRow; }
                else             { src = Bl; rbase = bn; rstride = bRow; }
            } else if (NPROD == 2) {
                if (t == 0)      { src = Ah; rbase = bm; rstride = aRow; }
                else if (t == 1) { src = Al; rbase = bm; rstride = aRow; }
                else             { src = Bh; rbase = bn; rstride = bRow; }
            } else {
                if (t == 0)      { src = Ah; rbase = bm; rstride = aRow; }
                else             { src = Bh; rbase = bn; rstride = bRow; }
            }
            uint32_t tb = st + t * TILE_SZ;
#pragma unroll
            for (int it = 0; it < 2; it++) {
                int u = tid + it * 256;            // 512 units per tile
                int row = u >> 2, ch = u & 3;
                cp16(tb + row * PITCH + ch * 16,
                     src + (long long)(rbase + row) * rstride + kofs + ch * 8);
            }
        }
        CP_COMMIT();
    };

    float acc[2][8][4];
#pragma unroll
    for (int i = 0; i < 2; i++)
#pragma unroll
        for (int j = 0; j < 8; j++)
#pragma unroll
            for (int r = 0; r < 4; r++) acc[i][j][r] = 0.f;

    load_chunk(0, 0);
    CP_WAIT_0();
    __syncthreads();

    for (int c = 0; c < nc; c++) {
        int s = c & 1;
        if (c + 1 < nc) load_chunk(c + 1, s ^ 1);

        uint32_t st = sbase + s * STAGE;
        uint32_t aHB = st, aLB = st + TILE_SZ;
        uint32_t bHB = st + (NT - (NPROD == 3 ? 2 : 1)) * TILE_SZ;
        uint32_t bLB = st + (NT - 1) * TILE_SZ;      // only used for NPROD==3

#pragma unroll
        for (int ks = 0; ks < 2; ks++) {
            const int chcol = (ks * 2 + (lane >> 4)) * 16;
            uint32_t ah[2][4], al[2][4];
#pragma unroll
            for (int t = 0; t < 2; t++) {
                int row = wm * 32 + t * 16 + (lane & 15);
                uint32_t off = row * PITCH + chcol;
                ldsm4(ah[t][0], ah[t][1], ah[t][2], ah[t][3], aHB + off);
                if (NPROD >= 2)
                    ldsm4(al[t][0], al[t][1], al[t][2], al[t][3], aLB + off);
            }
            uint32_t bh[8][2], bl[8][2];
#pragma unroll
            for (int jj = 0; jj < 4; jj++) {
                int row = wn * 64 + jj * 16 + (lane & 15);
                uint32_t off = row * PITCH + chcol;
                uint32_t r0, r1, r2, r3;
                ldsm4(r0, r1, r2, r3, bHB + off);
                bh[jj * 2][0] = r0; bh[jj * 2][1] = r2;
                bh[jj * 2 + 1][0] = r1; bh[jj * 2 + 1][1] = r3;
                if (NPROD == 3) {
                    ldsm4(r0, r1, r2, r3, bLB + off);
                    bl[jj * 2][0] = r0; bl[jj * 2][1] = r2;
                    bl[jj * 2 + 1][0] = r1; bl[jj * 2 + 1][1] = r3;
                }
            }
#pragma unroll
            for (int i = 0; i < 2; i++)
#pragma unroll
                for (int j = 0; j < 8; j++)
                    mma16816(acc[i][j], ah[i], bh[j]);
            if (NPROD >= 2) {
#pragma unroll
                for (int i = 0; i < 2; i++)
#pragma unroll
                    for (int j = 0; j < 8; j++)
                        mma16816(acc[i][j], al[i], bh[j]);
            }
            if (NPROD == 3) {
#pragma unroll
                for (int i = 0; i < 2; i++)
#pragma unroll
                    for (int j = 0; j < 8; j++)
                        mma16816(acc[i][j], ah[i], bl[j]);
            }
        }
        CP_WAIT_0();
        __syncthreads();
    }

    // --------- epilogue ---------
    if (MODE == 2 || MODE == 3) {
        float* o0 = p.outF + (long long)z * p.oBatch;
        const int mB = bm + wm * 32 + (lane >> 2);
        const int nB = bn + wn * 64 + (lane & 3) * 2;
#pragma unroll
        for (int i = 0; i < 2; i++)
#pragma unroll
            for (int j = 0; j < 8; j++) {
                int m = mB + i * 16, n = nB + j * 8;
                float v0 = acc[i][j][0], v1 = acc[i][j][1];
                float v2 = acc[i][j][2], v3 = acc[i][j][3];
                if (MODE == 3) {   // exp(logit) — no max shift needed (|l|<45)
                    v0 = __expf(v0); v1 = __expf(v1);
                    v2 = __expf(v2); v3 = __expf(v3);
                }
                *(float2*)(o0 + (long long)m * p.oRow + n)       = make_float2(v0, v1);
                *(float2*)(o0 + (long long)(m + 8) * p.oRow + n) = make_float2(v2, v3);
            }
    } else {
        const int sel = bn >> 9;                    // 0=Q 1=K 2=V
        if (sel < 2) {
            __half* o0 = sel ? p.kh : p.qh;
            __half* o1 = sel ? p.kl : p.ql;
            const int mB = bm + wm * 32 + (lane >> 2);
            const int nW = wn * 64 + (lane & 3) * 2;
#pragma unroll
            for (int i = 0; i < 2; i++)
#pragma unroll
                for (int j = 0; j < 8; j++) {
                    int m = mB + i * 16;
                    int nl = (bn & 511) + nW + j * 8;
                    float b0 = p.bias[bn + nW + j * 8], b1 = p.bias[bn + nW + j * 8 + 1];
                    unsigned short h0, l0, h1, l1;
#pragma unroll
                    for (int hf = 0; hf < 2; hf++) {
                        int mm = m + hf * 8;
                        split2h(acc[i][j][hf * 2 + 0] + b0, h0, l0);
                        split2h(acc[i][j][hf * 2 + 1] + b1, h1, l1);
                        long long a = (long long)mm * H_DIM + nl;
                        *(ushort2*)(o0 + a) = make_ushort2(h0, h1);
                        *(ushort2*)(o1 + a) = make_ushort2(l0, l1);
                    }
                }
        } else {
            // V: transposed fp16 out via smem staging [128][129] u32
            uint32_t* stg = (uint32_t*)smem;
            __syncthreads();
#pragma unroll
            for (int i = 0; i < 2; i++)
#pragma unroll
                for (int j = 0; j < 8; j++)
#pragma unroll
                    for (int r = 0; r < 4; r++) {
                        int ml = wm * 32 + i * 16 + (r >> 1) * 8 + (lane >> 2);
                        int nl = wn * 64 + j * 8 + (lane & 3) * 2 + (r & 1);
                        float v = acc[i][j][r] + p.bias[bn + nl];
                        stg[ml * 129 + nl] = (uint32_t)__half_as_ushort(__float2half_rn(v));
                    }
            __syncthreads();
            int col = tid >> 1, rch = (tid & 1) * 64;
            int n = (bn & 511) + col;
            long long base = (long long)n * NROWS + bm + rch;
#pragma unroll
            for (int r = 0; r < 64; r += 2) {
                uint32_t w0 = stg[(rch + r) * 129 + col];
                uint32_t w1 = stg[(rch + r + 1) * 129 + col];
                *(ushort2*)(p.vt + base + r) =
                    make_ushort2((unsigned short)w0, (unsigned short)w1);
            }
        }
    }
}

// ---------------- prep: pe table (fp32, matching reference) + weights -------
__global__ void prep_kernel(const float* __restrict__ Wq, const float* __restrict__ Wk,
                            const float* __restrict__ Wv,
                            const float* __restrict__ bq, const float* __restrict__ bk,
                            const float* __restrict__ bv,
                            float* __restrict__ pe, float* __restrict__ bias,
                            __half* __restrict__ wh, __half* __restrict__ wl) {
    int b = blockIdx.x, t = threadIdx.x;
    if (b < 4096) {                                    // pe: 1M elements, pure fp32
        int idx = b * 256 + t;
        int h = idx & (H_DIM - 1);
        int s = idx >> 9;
        int j = (h < H_DIM / 2) ? h : h - H_DIM / 2;
        float d   = expf((float)(2 * j) * (-9.210340371976184f / 512.0f));
        float ang = (float)s * d;
        pe[idx] = (h < H_DIM / 2) ? sinf(ang) : cosf(ang);
    } else if (b < 4096 + 3072) {                      // stacked weights 1536x512
        int idx = (b - 4096) * 256 + t;
        int w = idx >> 18;
        int off = idx & 262143;
        const float* W = (w == 0) ? Wq : (w == 1) ? Wk : Wv;
        unsigned short h, l;
        split2h(W[off], h, l);
        wh[idx] = __ushort_as_half(h);
        wl[idx] = __ushort_as_half(l);
    } else {                                           // stacked bias 1536
        int i = (b - 4096 - 3072) * 256 + t;
        if (i < NSTACK)
            bias[i] = (i < 512) ? bq[i] : (i < 1024) ? bk[i - 512] : bv[i - 1024];
    }
}

__global__ void conv_x_kernel(const float* __restrict__ in, const float* __restrict__ pe,
                              __half* __restrict__ xh, __half* __restrict__ xl) {
    int i = blockIdx.x * blockDim.x + threadIdx.x;
    if (i >= NROWS * H_DIM) return;
    float v = in[i] + pe[i & (S_DIM * H_DIM - 1)];
    unsigned short h, l;
    split2h(v, h, l);
    xh[i] = __ushort_as_half(h);
    xl[i] = __ushort_as_half(l);
}

// ---------------- normalize: e(fp32) -> probs(fp16), sum only ---------------
__global__ __launch_bounds__(256) void norm_kernel(const float* __restrict__ e,
                                                   __half* __restrict__ ph) {
    const float* row = e + (long long)blockIdx.x * S_DIM;
    long long obase = (long long)blockIdx.x * S_DIM + threadIdx.x * 8;
    int tid = threadIdx.x;
    __shared__ float red[256];

    float4 a = *(const float4*)(row + tid * 8);
    float4 b = *(const float4*)(row + tid * 8 + 4);
    float sum = a.x + a.y + a.z + a.w + b.x + b.y + b.z + b.w;
    red[tid] = sum; __syncthreads();
    for (int s = 128; s > 0; s >>= 1) {
        if (tid < s) red[tid] += red[tid + s];
        __syncthreads();
    }
    float inv = 1.f / red[0];
    __half2 w0 = __floats2half2_rn(a.x * inv, a.y * inv);
    __half2 w1 = __floats2half2_rn(a.z * inv, a.w * inv);
    __half2 w2 = __floats2half2_rn(b.x * inv, b.y * inv);
    __half2 w3 = __floats2half2_rn(b.z * inv, b.w * inv);
    *(__half2*)(ph + obase + 0) = w0;
    *(__half2*)(ph + obase + 2) = w1;
    *(__half2*)(ph + obase + 4) = w2;
    *(__half2*)(ph + obase + 6) = w3;
}

// ---------------- launch ----------------------------------------------------
extern "C" void kernel_launch(void* const* d_in, const int* in_sizes, int n_in,
                              void* d_out, int out_size) {
    const float* in_e = (const float*)d_in[0];
    const float* Wq   = (const float*)d_in[1];
    const float* bq   = (const float*)d_in[2];
    const float* Wk   = (const float*)d_in[3];
    const float* bk   = (const float*)d_in[4];
    const float* Wv   = (const float*)d_in[5];
    const float* bv   = (const float*)d_in[6];
    float* out = (float*)d_out;

    const int SMEM3 = 2 * 4 * TILE_SZ;   // 81920
    const int SMEM2 = 2 * 3 * TILE_SZ;   // 61440
    const int SMEM1 = 2 * 2 * TILE_SZ;   // 40960
    cudaFuncSetAttribute(tc_gemm<3,0>, cudaFuncAttributeMaxDynamicSharedMemorySize, SMEM3);
    cudaFuncSetAttribute(tc_gemm<2,3>, cudaFuncAttributeMaxDynamicSharedMemorySize, SMEM2);
    cudaFuncSetAttribute(tc_gemm<1,2>, cudaFuncAttributeMaxDynamicSharedMemorySize, SMEM1);

#define SYM(v, s) void* v##_; cudaGetSymbolAddress(&v##_, s);
    SYM(pe, g_pe) SYM(bias, g_bias) SYM(xh, g_xh) SYM(xl, g_xl)
    SYM(wh, g_wh) SYM(wl, g_wl)
    SYM(qh, g_qh) SYM(ql, g_ql) SYM(kh, g_kh) SYM(kl, g_kl)
    SYM(vt, g_vt) SYM(sc, g_sc) SYM(sph, g_ph)
#undef SYM

    // 0: prep (fp32 pe + stacked weights + stacked bias)
    prep_kernel<<<4096 + 3072 + 6, 256>>>(Wq, Wk, Wv, bq, bk, bv,
        (float*)pe_, (float*)bias_, (__half*)wh_, (__half*)wl_);
    // 1: conv_x
    conv_x_kernel<<<(NROWS * H_DIM + 255) / 256, 256>>>(in_e, (float*)pe_,
        (__half*)xh_, (__half*)xl_);

    GemmParams p;
    p.qh = (__half*)qh_; p.ql = (__half*)ql_;
    p.kh = (__half*)kh_; p.kl = (__half*)kl_;
    p.vt = (__half*)vt_;

    // 2: fused QKV: [16384,1536] = x @ Wstack^T + b (3-product)
    p.Ah = (const __half*)xh_; p.Al = (const __half*)xl_;
    p.Bh = (const __half*)wh_; p.Bl = (const __half*)wl_;
    p.bias = (const float*)bias_;
    p.aBatch = 0; p.bBatch = 0; p.aRow = H_DIM; p.bRow = H_DIM; p.K = H_DIM;
    p.outF = nullptr; p.oBatch = 0; p.oRow = 0;
    dim3 gqkv(NSTACK / 128, NROWS / 128, 1);
    tc_gemm<3,0><<<gqkv, 256, SMEM3>>>(p);

    // 3: e = exp((qh+ql) @ kh^T) per batch (2-product, MODE 3: exp epilogue)
    p.Ah = (const __half*)qh_; p.Al = (const __half*)ql_;
    p.Bh = (const __half*)kh_; p.Bl = nullptr;
    p.aBatch = (long long)S_DIM * H_DIM; p.bBatch = (long long)S_DIM * H_DIM;
    p.aRow = H_DIM; p.bRow = H_DIM; p.K = H_DIM;
    p.outF = (float*)sc_;
    p.oBatch = (long long)S_DIM * S_DIM; p.oRow = S_DIM;
    dim3 gs(S_DIM / 128, S_DIM / 128, B_DIM);
    tc_gemm<2,3><<<gs, 256, SMEM2>>>(p);

    // 4: normalize -> fp16 probs (sum + scale only; exp already done)
    norm_kernel<<<B_DIM * S_DIM, 256>>>((const float*)sc_, (__half*)sph_);

    // 5: out = probs @ v (single product, NT with B = vT)
    p.Ah = (const __half*)sph_; p.Al = nullptr;
    p.Bh = (const __half*)vt_;  p.Bl = nullptr;
    p.aBatch = (long long)S_DIM * S_DIM; p.bBatch = S_DIM;
    p.aRow = S_DIM; p.bRow = NROWS; p.K = S_DIM;
    p.outF = out;
    p.oBatch = (long long)S_DIM * H_DIM; p.oRow = H_DIM;
    dim3 go(H_DIM / 128, S_DIM / 128, B_DIM);
    tc_gemm<1,2><<<go, 256, SMEM1>>>(p);
}

// round 15
// speedup vs baseline: 1.3872x; 1.0326x over previous
#include <cuda_runtime.h>
#include <cuda_fp16.h>
#include <cstdint>
#include <math.h>

#define B_DIM 8
#define S_DIM 2048
#define H_DIM 512
#define NROWS (B_DIM * S_DIM)          // 16384
#define NSTACK (3 * H_DIM)             // 1536

// ---------------- scratch (device globals; no allocations allowed) ----------
__device__ float g_pe[S_DIM * H_DIM];
__device__ float g_bias[NSTACK];
__device__ __half g_xh[NROWS * H_DIM], g_xl[NROWS * H_DIM];
__device__ __half g_wh[NSTACK * H_DIM], g_wl[NSTACK * H_DIM];   // stacked Wq,Wk,Wv
__device__ __half g_qh[NROWS * H_DIM], g_ql[NROWS * H_DIM];
__device__ __half g_kh[NROWS * H_DIM];
__device__ __half g_vt[H_DIM * NROWS];                          // v transposed, fp16
__device__ float g_sc[(long long)B_DIM * S_DIM * S_DIM];        // exp(logits), fp32
__device__ float g_pr[B_DIM * 16 * S_DIM];                      // row partials [z][bx][m]
__device__ float g_rinv[B_DIM * S_DIM];                         // 1/rowsum

// ---------------- helpers ----------------------------------------------
__device__ __forceinline__ uint32_t smem_u32(const void* p) {
    uint32_t a;
    asm("{ .reg .u64 t; cvta.to.shared.u64 t, %1; cvt.u32.u64 %0, t; }" : "=r"(a) : "l"(p));
    return a;
}
__device__ __forceinline__ void cp16(uint32_t dst, const void* src) {
    asm volatile("cp.async.cg.shared.global [%0], [%1], 16;"
                 :: "r"(dst), "l"(__cvta_generic_to_global(src)));
}
#define CP_COMMIT() asm volatile("cp.async.commit_group;" ::: "memory")
#define CP_WAIT_0() asm volatile("cp.async.wait_group 0;" ::: "memory")

__device__ __forceinline__ void ldsm4(uint32_t& r0, uint32_t& r1, uint32_t& r2, uint32_t& r3,
                                      uint32_t addr) {
    asm volatile("ldmatrix.sync.aligned.m8n8.x4.shared.b16 {%0,%1,%2,%3}, [%4];"
                 : "=r"(r0), "=r"(r1), "=r"(r2), "=r"(r3) : "r"(addr));
}
__device__ __forceinline__ void mma16816(float* c, const uint32_t* a, const uint32_t* b) {
    asm volatile(
        "mma.sync.aligned.m16n8k16.row.col.f32.f16.f16.f32 "
        "{%0,%1,%2,%3}, {%4,%5,%6,%7}, {%8,%9}, {%0,%1,%2,%3};"
        : "+f"(c[0]), "+f"(c[1]), "+f"(c[2]), "+f"(c[3])
        : "r"(a[0]), "r"(a[1]), "r"(a[2]), "r"(a[3]), "r"(b[0]), "r"(b[1]));
}
__device__ __forceinline__ void split2h(float v, unsigned short& h, unsigned short& l) {
    __half hh = __float2half_rn(v);
    __half ll = __float2half_rn(v - __half2float(hh));
    h = __half_as_ushort(hh);
    l = __half_as_ushort(ll);
}

// ---------------- split-fp16 HMMA GEMM: C = A * B^T -------------------------
// Block tile 128x128, BK=32, 256 threads (4x2 warps), warp tile 32x64.
// SMEM rows: pitch 80B (64B data + 16B pad) -> conflict-free ldsm.
// NPROD=3: A hi/lo x B hi/lo. NPROD=2: A hi/lo x B single. NPROD=1: single.
// MODE 0: fused QKV epilogue. MODE 3: exp(fp32) out + row partials.
// MODE 4: A = fp32 e loaded via LDG, scaled by rowinv, converted to fp16.
struct GemmParams {
    const __half *Ah, *Al, *Bh, *Bl;
    const float* Af;                    // MODE 4: fp32 A source
    const float* rinv;                  // MODE 4: per-row 1/sum
    const float* bias;
    float* partials;                    // MODE 3
    long long aBatch, bBatch;
    int aRow, bRow, K;
    __half *qh, *ql, *kh, *vt;          // MODE 0 outputs
    float* outF;                        // MODE 3/4 output
    long long oBatch;
    int oRow;
};

#define PITCH   80
#define TILE_SZ (128 * PITCH)           // 10240

template<int NPROD, int MODE>
__global__ __launch_bounds__(256, 2) void tc_gemm(GemmParams p) {
    constexpr int NT = (NPROD == 3) ? 4 : (NPROD == 2) ? 3 : 2;
    constexpr int STAGE = NT * TILE_SZ;
    extern __shared__ char smem[];
    uint32_t sbase = smem_u32(smem);

    const int tid = threadIdx.x;
    const int wid = tid >> 5, lane = tid & 31;
    const int wm = wid & 3, wn = wid >> 2;          // warp tile (wm*32, wn*64)

    const int bm = blockIdx.y * 128, bn = blockIdx.x * 128, z = blockIdx.z;
    const __half* Ah = p.Ah + (long long)z * p.aBatch;
    const __half* Al = p.Al + (long long)z * p.aBatch;
    const __half* Bh = p.Bh + (long long)z * p.bBatch;
    const __half* Bl = p.Bl + (long long)z * p.bBatch;
    const float*  Af = (MODE == 4) ? p.Af + (long long)z * p.aBatch : nullptr;
    const int aRow = p.aRow, bRow = p.bRow;

    const int nc = p.K >> 5;

    // MODE 4: rowinv for this CTA's 128 rows in smem (after stage area)
    float* rinvs = (float*)(smem + 2 * STAGE);
    if (MODE == 4) {
        if (tid < 128) rinvs[tid] = p.rinv[(long long)z * S_DIM + bm + tid];
        __syncthreads();
    }

    // B-side (and A-side for NPROD>=2) async tile loads
    auto load_chunk = [&](int c, int s) {
        uint32_t st = sbase + s * STAGE;
        long long kofs = (long long)c * 32;
#pragma unroll
        for (int t = 0; t < NT; t++) {
            const __half* src;
            int rbase, rstride;
            if (NPROD == 3) {
                if (t == 0)      { src = Ah; rbase = bm; rstride = aRow; }
                else if (t == 1) { src = Al; rbase = bm; rstride = aRow; }
                else if (t == 2) { src = Bh; rbase = bn; rstride = bRow; }
                else             { src = Bl; rbase = bn; rstride = bRow; }
            } else if (NPROD == 2) {
                if (t == 0)      { src = Ah; rbase = bm; rstride = aRow; }
                else if (t == 1) { src = Al; rbase = bm; rstride = aRow; }
                else             { src = Bh; rbase = bn; rstride = bRow; }
            } else {
                if (MODE == 4 && t == 0) continue;   // A handled manually
                if (t == 0)      { src = Ah; rbase = bm; rstride = aRow; }
                else             { src = Bh; rbase = bn; rstride = bRow; }
            }
            uint32_t tb = st + t * TILE_SZ;
#pragma unroll
            for (int it = 0; it < 2; it++) {
                int u = tid + it * 256;            // 512 units per tile
                int row = u >> 2, ch = u & 3;
                cp16(tb + row * PITCH + ch * 16,
                     src + (long long)(rbase + row) * rstride + kofs + ch * 8);
            }
        }
        CP_COMMIT();
    };

    // MODE 4 manual A path: LDG fp32 -> scale -> fp16 -> STS
    float4 areg[4];
    auto ldg_a = [&](int c) {
#pragma unroll
        for (int it = 0; it < 4; it++) {
            int u = tid + it * 256;                // 1024 float4 units
            int row = u >> 3, ch = u & 7;
            areg[it] = *(const float4*)(Af + (long long)(bm + row) * aRow + c * 32 + ch * 4);
        }
    };
    auto sts_a = [&](int s) {
        uint32_t st = sbase + s * STAGE;
#pragma unroll
        for (int it = 0; it < 4; it++) {
            int u = tid + it * 256;
            int row = u >> 3, ch = u & 7;
            float sc = rinvs[row];
            __half2 h01 = __floats2half2_rn(areg[it].x * sc, areg[it].y * sc);
            __half2 h23 = __floats2half2_rn(areg[it].z * sc, areg[it].w * sc);
            uint2 w;
            w.x = *(uint32_t*)&h01; w.y = *(uint32_t*)&h23;
            *(uint2*)(smem + (st - sbase) + row * PITCH + ch * 8) = w;
        }
    };

    float acc[2][8][4];
#pragma unroll
    for (int i = 0; i < 2; i++)
#pragma unroll
        for (int j = 0; j < 8; j++)
#pragma unroll
            for (int r = 0; r < 4; r++) acc[i][j][r] = 0.f;

    // prologue
    if (MODE == 4) { ldg_a(0); }
    load_chunk(0, 0);
    if (MODE == 4) { sts_a(0); }
    CP_WAIT_0();
    __syncthreads();

    for (int c = 0; c < nc; c++) {
        int s = c & 1;
        if (c + 1 < nc) {
            if (MODE == 4) ldg_a(c + 1);
            load_chunk(c + 1, s ^ 1);
        }

        uint32_t st = sbase + s * STAGE;
        uint32_t aHB = st, aLB = st + TILE_SZ;
        uint32_t bHB = st + (NT - (NPROD == 3 ? 2 : 1)) * TILE_SZ;
        uint32_t bLB = st + (NT - 1) * TILE_SZ;

#pragma unroll
        for (int ks = 0; ks < 2; ks++) {
            const int chcol = (ks * 2 + (lane >> 4)) * 16;
            uint32_t ah[2][4], al[2][4];
#pragma unroll
            for (int t = 0; t < 2; t++) {
                int row = wm * 32 + t * 16 + (lane & 15);
                uint32_t off = row * PITCH + chcol;
                ldsm4(ah[t][0], ah[t][1], ah[t][2], ah[t][3], aHB + off);
                if (NPROD >= 2)
                    ldsm4(al[t][0], al[t][1], al[t][2], al[t][3], aLB + off);
            }
            uint32_t bh[8][2], bl[8][2];
#pragma unroll
            for (int jj = 0; jj < 4; jj++) {
                int row = wn * 64 + jj * 16 + (lane & 15);
                uint32_t off = row * PITCH + chcol;
                uint32_t r0, r1, r2, r3;
                ldsm4(r0, r1, r2, r3, bHB + off);
                bh[jj * 2][0] = r0; bh[jj * 2][1] = r2;
                bh[jj * 2 + 1][0] = r1; bh[jj * 2 + 1][1] = r3;
                if (NPROD == 3) {
                    ldsm4(r0, r1, r2, r3, bLB + off);
                    bl[jj * 2][0] = r0; bl[jj * 2][1] = r2;
                    bl[jj * 2 + 1][0] = r1; bl[jj * 2 + 1][1] = r3;
                }
            }
#pragma unroll
            for (int i = 0; i < 2; i++)
#pragma unroll
                for (int j = 0; j < 8; j++)
                    mma16816(acc[i][j], ah[i], bh[j]);
            if (NPROD >= 2) {
#pragma unroll
                for (int i = 0; i < 2; i++)
#pragma unroll
                    for (int j = 0; j < 8; j++)
                        mma16816(acc[i][j], al[i], bh[j]);
            }
            if (NPROD == 3) {
#pragma unroll
                for (int i = 0; i < 2; i++)
#pragma unroll
                    for (int j = 0; j < 8; j++)
                        mma16816(acc[i][j], ah[i], bl[j]);
            }
        }
        if (MODE == 4 && c + 1 < nc) sts_a(s ^ 1);
        CP_WAIT_0();
        __syncthreads();
    }

    // --------- epilogue ---------
    if (MODE == 3 || MODE == 4) {
        float* o0 = p.outF + (long long)z * p.oBatch;
        const int mB = bm + wm * 32 + (lane >> 2);
        const int nB = bn + wn * 64 + (lane & 3) * 2;
        float rs[2][2] = {{0.f, 0.f}, {0.f, 0.f}};
#pragma unroll
        for (int i = 0; i < 2; i++)
#pragma unroll
            for (int j = 0; j < 8; j++) {
                int m = mB + i * 16, n = nB + j * 8;
                float v0 = acc[i][j][0], v1 = acc[i][j][1];
                float v2 = acc[i][j][2], v3 = acc[i][j][3];
                if (MODE == 3) {       // exp(logit); |logit| < 45, no shift needed
                    v0 = __expf(v0); v1 = __expf(v1);
                    v2 = __expf(v2); v3 = __expf(v3);
                    rs[i][0] += v0 + v1;
                    rs[i][1] += v2 + v3;
                }
                *(float2*)(o0 + (long long)m * p.oRow + n)       = make_float2(v0, v1);
                *(float2*)(o0 + (long long)(m + 8) * p.oRow + n) = make_float2(v2, v3);
            }
        if (MODE == 3) {
            // reduce over the 4 lanes sharing each row (lane&3), then across wn
#pragma unroll
            for (int off = 1; off < 4; off <<= 1) {
#pragma unroll
                for (int i = 0; i < 2; i++) {
                    rs[i][0] += __shfl_xor_sync(0xFFFFFFFF, rs[i][0], off);
                    rs[i][1] += __shfl_xor_sync(0xFFFFFFFF, rs[i][1], off);
                }
            }
            float* spar = (float*)smem;            // [2][128]
            __syncthreads();
            if ((lane & 3) == 0) {
#pragma unroll
                for (int i = 0; i < 2; i++)
#pragma unroll
                    for (int hf = 0; hf < 2; hf++) {
                        int r = wm * 32 + i * 16 + hf * 8 + (lane >> 2);
                        spar[wn * 128 + r] = rs[i][hf];
                    }
            }
            __syncthreads();
            if (tid < 128) {
                float v = spar[tid] + spar[128 + tid];
                p.partials[((long long)z * 16 + blockIdx.x) * S_DIM + bm + tid] = v;
            }
        }
    } else {
        const int sel = bn >> 9;                    // 0=Q 1=K 2=V
        if (sel < 2) {
            __half* o0 = sel ? p.kh : p.qh;
            __half* o1 = p.ql;                      // lo only needed for Q
            const int mB = bm + wm * 32 + (lane >> 2);
            const int nW = wn * 64 + (lane & 3) * 2;
#pragma unroll
            for (int i = 0; i < 2; i++)
#pragma unroll
                for (int j = 0; j < 8; j++) {
                    int m = mB + i * 16;
                    int nl = (bn & 511) + nW + j * 8;
                    float b0 = p.bias[bn + nW + j * 8], b1 = p.bias[bn + nW + j * 8 + 1];
                    unsigned short h0, l0, h1, l1;
#pragma unroll
                    for (int hf = 0; hf < 2; hf++) {
                        int mm = m + hf * 8;
                        split2h(acc[i][j][hf * 2 + 0] + b0, h0, l0);
                        split2h(acc[i][j][hf * 2 + 1] + b1, h1, l1);
                        long long a = (long long)mm * H_DIM + nl;
                        *(ushort2*)(o0 + a) = make_ushort2(h0, h1);
                        if (sel == 0)
                            *(ushort2*)(o1 + a) = make_ushort2(l0, l1);
                    }
                }
        } else {
            // V: transposed fp16 out via smem staging [128][129] u32
            uint32_t* stg = (uint32_t*)smem;
            __syncthreads();
#pragma unroll
            for (int i = 0; i < 2; i++)
#pragma unroll
                for (int j = 0; j < 8; j++)
#pragma unroll
                    for (int r = 0; r < 4; r++) {
                        int ml = wm * 32 + i * 16 + (r >> 1) * 8 + (lane >> 2);
                        int nl = wn * 64 + j * 8 + (lane & 3) * 2 + (r & 1);
                        float v = acc[i][j][r] + p.bias[bn + nl];
                        stg[ml * 129 + nl] = (uint32_t)__half_as_ushort(__float2half_rn(v));
                    }
            __syncthreads();
            int col = tid >> 1, rch = (tid & 1) * 64;
            int n = (bn & 511) + col;
            long long base = (long long)n * NROWS + bm + rch;
#pragma unroll
            for (int r = 0; r < 64; r += 2) {
                uint32_t w0 = stg[(rch + r) * 129 + col];
                uint32_t w1 = stg[(rch + r + 1) * 129 + col];
                *(ushort2*)(p.vt + base + r) =
                    make_ushort2((unsigned short)w0, (unsigned short)w1);
            }
        }
    }
}

// ---------------- prep: pe table (fp32) + stacked weights/bias --------------
__global__ void prep_kernel(const float* __restrict__ Wq, const float* __restrict__ Wk,
                            const float* __restrict__ Wv,
                            const float* __restrict__ bq, const float* __restrict__ bk,
                            const float* __restrict__ bv,
                            float* __restrict__ pe, float* __restrict__ bias,
                            __half* __restrict__ wh, __half* __restrict__ wl) {
    int b = blockIdx.x, t = threadIdx.x;
    if (b < 4096) {
        int idx = b * 256 + t;
        int h = idx & (H_DIM - 1);
        int s = idx >> 9;
        int j = (h < H_DIM / 2) ? h : h - H_DIM / 2;
        float d   = expf((float)(2 * j) * (-9.210340371976184f / 512.0f));
        float ang = (float)s * d;
        pe[idx] = (h < H_DIM / 2) ? sinf(ang) : cosf(ang);
    } else if (b < 4096 + 3072) {
        int idx = (b - 4096) * 256 + t;
        int w = idx >> 18;
        int off = idx & 262143;
        const float* W = (w == 0) ? Wq : (w == 1) ? Wk : Wv;
        unsigned short h, l;
        split2h(W[off], h, l);
        wh[idx] = __ushort_as_half(h);
        wl[idx] = __ushort_as_half(l);
    } else {
        int i = (b - 4096 - 3072) * 256 + t;
        if (i < NSTACK)
            bias[i] = (i < 512) ? bq[i] : (i < 1024) ? bk[i - 512] : bv[i - 1024];
    }
}

__global__ void conv_x_kernel(const float* __restrict__ in, const float* __restrict__ pe,
                              __half* __restrict__ xh, __half* __restrict__ xl) {
    int i = blockIdx.x * blockDim.x + threadIdx.x;
    if (i >= NROWS * H_DIM) return;
    float v = in[i] + pe[i & (S_DIM * H_DIM - 1)];
    unsigned short h, l;
    split2h(v, h, l);
    xh[i] = __ushort_as_half(h);
    xl[i] = __ushort_as_half(l);
}

// ---------------- rowinv: reduce 16 partials per row ------------------------
__global__ void rowinv_kernel(const float* __restrict__ pr, float* __restrict__ rinv) {
    int idx = blockIdx.x * blockDim.x + threadIdx.x;     // [0, 16384)
    if (idx >= B_DIM * S_DIM) return;
    int z = idx >> 11, m = idx & (S_DIM - 1);
    const float* base = pr + (long long)z * 16 * S_DIM + m;
    float s = 0.f;
#pragma unroll
    for (int j = 0; j < 16; j++) s += base[j * S_DIM];
    rinv[idx] = 1.f / s;
}

// ---------------- launch ----------------------------------------------------
extern "C" void kernel_launch(void* const* d_in, const int* in_sizes, int n_in,
                              void* d_out, int out_size) {
    const float* in_e = (const float*)d_in[0];
    const float* Wq   = (const float*)d_in[1];
    const float* bq   = (const float*)d_in[2];
    const float* Wk   = (const float*)d_in[3];
    const float* bk   = (const float*)d_in[4];
    const float* Wv   = (const float*)d_in[5];
    const float* bv   = (const float*)d_in[6];
    float* out = (float*)d_out;

    const int SMEM3 = 2 * 4 * TILE_SZ;          // 81920
    const int SMEM2 = 2 * 3 * TILE_SZ;          // 61440
    const int SMEM4 = 2 * 2 * TILE_SZ + 512;    // 41472 (stages + rinv)
    cudaFuncSetAttribute(tc_gemm<3,0>, cudaFuncAttributeMaxDynamicSharedMemorySize, SMEM3);
    cudaFuncSetAttribute(tc_gemm<2,3>, cudaFuncAttributeMaxDynamicSharedMemorySize, SMEM2);
    cudaFuncSetAttribute(tc_gemm<1,4>, cudaFuncAttributeMaxDynamicSharedMemorySize, SMEM4);

#define SYM(v, s) void* v##_; cudaGetSymbolAddress(&v##_, s);
    SYM(pe, g_pe) SYM(bias, g_bias) SYM(xh, g_xh) SYM(xl, g_xl)
    SYM(wh, g_wh) SYM(wl, g_wl)
    SYM(qh, g_qh) SYM(ql, g_ql) SYM(kh, g_kh)
    SYM(vt, g_vt) SYM(sc, g_sc) SYM(pr, g_pr) SYM(rinv, g_rinv)
#undef SYM

    // 0: prep
    prep_kernel<<<4096 + 3072 + 6, 256>>>(Wq, Wk, Wv, bq, bk, bv,
        (float*)pe_, (float*)bias_, (__half*)wh_, (__half*)wl_);
    // 1: conv_x
    conv_x_kernel<<<(NROWS * H_DIM + 255) / 256, 256>>>(in_e, (float*)pe_,
        (__half*)xh_, (__half*)xl_);

    GemmParams p;
    p.qh = (__half*)qh_; p.ql = (__half*)ql_;
    p.kh = (__half*)kh_; p.vt = (__half*)vt_;
    p.Af = nullptr; p.rinv = nullptr; p.partials = nullptr;

    // 2: fused QKV: [16384,1536] = x @ Wstack^T + b (3-product)
    p.Ah = (const __half*)xh_; p.Al = (const __half*)xl_;
    p.Bh = (const __half*)wh_; p.Bl = (const __half*)wl_;
    p.bias = (const float*)bias_;
    p.aBatch = 0; p.bBatch = 0; p.aRow = H_DIM; p.bRow = H_DIM; p.K = H_DIM;
    p.outF = nullptr; p.oBatch = 0; p.oRow = 0;
    dim3 gqkv(NSTACK / 128, NROWS / 128, 1);
    tc_gemm<3,0><<<gqkv, 256, SMEM3>>>(p);

    // 3: e = exp((qh+ql) @ kh^T), + per-CTA row partials (2-product, MODE 3)
    p.Ah = (const __half*)qh_; p.Al = (const __half*)ql_;
    p.Bh = (const __half*)kh_; p.Bl = nullptr;
    p.partials = (float*)pr_;
    p.aBatch = (long long)S_DIM * H_DIM; p.bBatch = (long long)S_DIM * H_DIM;
    p.aRow = H_DIM; p.bRow = H_DIM; p.K = H_DIM;
    p.outF = (float*)sc_;
    p.oBatch = (long long)S_DIM * S_DIM; p.oRow = S_DIM;
    dim3 gs(S_DIM / 128, S_DIM / 128, B_DIM);
    tc_gemm<2,3><<<gs, 256, SMEM2>>>(p);

    // 4: rowinv = 1 / rowsum
    rowinv_kernel<<<(B_DIM * S_DIM + 255) / 256, 256>>>((const float*)pr_, (float*)rinv_);

    // 5: out = (e * rowinv) @ v   (MODE 4: fp32 A + scale in load path)
    p.Ah = nullptr; p.Al = nullptr;
    p.Af = (const float*)sc_; p.rinv = (const float*)rinv_;
    p.Bh = (const __half*)vt_; p.Bl = nullptr;
    p.partials = nullptr;
    p.aBatch = (long long)S_DIM * S_DIM; p.bBatch = S_DIM;
    p.aRow = S_DIM; p.bRow = NROWS; p.K = S_DIM;
    p.outF = out;
    p.oBatch = (long long)S_DIM * H_DIM; p.oRow = H_DIM;
    dim3 go(H_DIM / 128, S_DIM / 128, B_DIM);
    tc_gemm<1,4><<<go, 256, SMEM4>>>(p);
}

// round 16
// speedup vs baseline: 1.4417x; 1.0393x over previous
#include <cuda_runtime.h>
#include <cuda_fp16.h>
#include <cstdint>
#include <math.h>

#define B_DIM 8
#define S_DIM 2048
#define H_DIM 512
#define NROWS (B_DIM * S_DIM)          // 16384
#define NSTACK (3 * H_DIM)             // 1536

// ---------------- scratch (device globals; no allocations allowed) ----------
__device__ float g_pe[S_DIM * H_DIM];
__device__ float g_bias[NSTACK];
__device__ __half g_xh[NROWS * H_DIM], g_xl[NROWS * H_DIM];
__device__ __half g_wh[NSTACK * H_DIM], g_wl[NSTACK * H_DIM];   // stacked Wq,Wk,Wv
__device__ __half g_qh[NROWS * H_DIM], g_ql[NROWS * H_DIM];
__device__ __half g_kh[NROWS * H_DIM];
__device__ __half g_vt[H_DIM * NROWS];                          // v transposed, fp16
__device__ float g_sc[(long long)B_DIM * S_DIM * S_DIM];        // exp(logits), fp32
__device__ float g_pr[B_DIM * 16 * S_DIM];                      // row partials [z][bx][m]
__device__ float g_rinv[B_DIM * S_DIM];                         // 1/rowsum

// ---------------- helpers ----------------------------------------------
__device__ __forceinline__ uint32_t smem_u32(const void* p) {
    uint32_t a;
    asm("{ .reg .u64 t; cvta.to.shared.u64 t, %1; cvt.u32.u64 %0, t; }" : "=r"(a) : "l"(p));
    return a;
}
__device__ __forceinline__ void cp16(uint32_t dst, const void* src) {
    asm volatile("cp.async.cg.shared.global [%0], [%1], 16;"
                 :: "r"(dst), "l"(__cvta_generic_to_global(src)));
}
#define CP_COMMIT() asm volatile("cp.async.commit_group;" ::: "memory")
#define CP_WAIT_0() asm volatile("cp.async.wait_group 0;" ::: "memory")

__device__ __forceinline__ void ldsm4(uint32_t& r0, uint32_t& r1, uint32_t& r2, uint32_t& r3,
                                      uint32_t addr) {
    asm volatile("ldmatrix.sync.aligned.m8n8.x4.shared.b16 {%0,%1,%2,%3}, [%4];"
                 : "=r"(r0), "=r"(r1), "=r"(r2), "=r"(r3) : "r"(addr));
}
__device__ __forceinline__ void mma16816(float* c, const uint32_t* a, const uint32_t* b) {
    asm volatile(
        "mma.sync.aligned.m16n8k16.row.col.f32.f16.f16.f32 "
        "{%0,%1,%2,%3}, {%4,%5,%6,%7}, {%8,%9}, {%0,%1,%2,%3};"
        : "+f"(c[0]), "+f"(c[1]), "+f"(c[2]), "+f"(c[3])
        : "r"(a[0]), "r"(a[1]), "r"(a[2]), "r"(a[3]), "r"(b[0]), "r"(b[1]));
}
__device__ __forceinline__ void split2h(float v, unsigned short& h, unsigned short& l) {
    __half hh = __float2half_rn(v);
    __half ll = __float2half_rn(v - __half2float(hh));
    h = __half_as_ushort(hh);
    l = __half_as_ushort(ll);
}

// ---------------- split-fp16 HMMA GEMM: C = A * B^T -------------------------
// Block tile 128x128, BK=32, 256 threads (4x2 warps), warp tile 32x64.
// SMEM rows: pitch 80B (64B data + 16B pad) -> conflict-free ldsm.
// NPROD=3: A hi/lo x B hi/lo. NPROD=2: A hi/lo x B single. NPROD=1: single.
// MODE 0: fused QKV epilogue (V blocks use 2 products). MODE 3: exp out +
// row partials. MODE 4: A = fp32 e via LDG, scaled by rowinv, to fp16.
struct GemmParams {
    const __half *Ah, *Al, *Bh, *Bl;
    const float* Af;                    // MODE 4: fp32 A source
    const float* rinv;                  // MODE 4: per-row 1/sum
    const float* bias;
    float* partials;                    // MODE 3
    long long aBatch, bBatch;
    int aRow, bRow, K;
    __half *qh, *ql, *kh, *vt;          // MODE 0 outputs
    float* outF;                        // MODE 3/4 output
    long long oBatch;
    int oRow;
};

#define PITCH   80
#define TILE_SZ (128 * PITCH)           // 10240

template<int NPROD, int MODE>
__global__ __launch_bounds__(256, 2) void tc_gemm(GemmParams p) {
    constexpr int NT = (NPROD == 3) ? 4 : (NPROD == 2) ? 3 : 2;
    constexpr int STAGE = NT * TILE_SZ;
    extern __shared__ char smem[];
    uint32_t sbase = smem_u32(smem);

    const int tid = threadIdx.x;
    const int wid = tid >> 5, lane = tid & 31;
    const int wm = wid & 3, wn = wid >> 2;          // warp tile (wm*32, wn*64)

    const int bm = blockIdx.y * 128, bn = blockIdx.x * 128, z = blockIdx.z;
    const __half* Ah = p.Ah + (long long)z * p.aBatch;
    const __half* Al = p.Al + (long long)z * p.aBatch;
    const __half* Bh = p.Bh + (long long)z * p.bBatch;
    const __half* Bl = p.Bl + (long long)z * p.bBatch;
    const float*  Af = (MODE == 4) ? p.Af + (long long)z * p.aBatch : nullptr;
    const int aRow = p.aRow, bRow = p.bRow;

    // MODE 0, V blocks (sel==2): skip the ah*bl product (v output is single
    // fp16 anyway; dropped term is below its rounding floor's amplification).
    const bool skipBl = (MODE == 0) && ((bn >> 9) == 2);

    const int nc = p.K >> 5;

    auto load_chunk = [&](int c, int s) {
        uint32_t st = sbase + s * STAGE;
        long long kofs = (long long)c * 32;
#pragma unroll
        for (int t = 0; t < NT; t++) {
            const __half* src;
            int rbase, rstride;
            if (NPROD == 3) {
                if (t == 3 && skipBl) continue;
                if (t == 0)      { src = Ah; rbase = bm; rstride = aRow; }
                else if (t == 1) { src = Al; rbase = bm; rstride = aRow; }
                else if (t == 2) { src = Bh; rbase = bn; rstride = bRow; }
                else             { src = Bl; rbase = bn; rstride = bRow; }
            } else if (NPROD == 2) {
                if (t == 0)      { src = Ah; rbase = bm; rstride = aRow; }
                else if (t == 1) { src = Al; rbase = bm; rstride = aRow; }
                else             { src = Bh; rbase = bn; rstride = bRow; }
            } else {
                if (MODE == 4 && t == 0) continue;   // A handled manually
                if (t == 0)      { src = Ah; rbase = bm; rstride = aRow; }
                else             { src = Bh; rbase = bn; rstride = bRow; }
            }
            uint32_t tb = st + t * TILE_SZ;
#pragma unroll
            for (int it = 0; it < 2; it++) {
                int u = tid + it * 256;            // 512 units per tile
                int row = u >> 2, ch = u & 3;
                cp16(tb + row * PITCH + ch * 16,
                     src + (long long)(rbase + row) * rstride + kofs + ch * 8);
            }
        }
        CP_COMMIT();
    };

    // MODE 4 manual A path: LDG fp32 -> scale -> fp16 -> STS
    float4 areg[4];
    auto ldg_a = [&](int c) {
#pragma unroll
        for (int it = 0; it < 4; it++) {
            int u = tid + it * 256;                // 1024 float4 units
            int row = u >> 3, ch = u & 7;
            areg[it] = *(const float4*)(Af + (long long)(bm + row) * aRow + c * 32 + ch * 4);
        }
    };
    float* rinvs = (float*)(smem + 2 * STAGE);
    if (MODE == 4) {
        if (tid < 128) rinvs[tid] = p.rinv[(long long)z * S_DIM + bm + tid];
        __syncthreads();
    }
    auto sts_a = [&](int s) {
        uint32_t st = sbase + s * STAGE;
#pragma unroll
        for (int it = 0; it < 4; it++) {
            int u = tid + it * 256;
            int row = u >> 3, ch = u & 7;
            float sc = rinvs[row];
            __half2 h01 = __floats2half2_rn(areg[it].x * sc, areg[it].y * sc);
            __half2 h23 = __floats2half2_rn(areg[it].z * sc, areg[it].w * sc);
            uint2 w;
            w.x = *(uint32_t*)&h01; w.y = *(uint32_t*)&h23;
            *(uint2*)(smem + (st - sbase) + row * PITCH + ch * 8) = w;
        }
    };

    float acc[2][8][4];
#pragma unroll
    for (int i = 0; i < 2; i++)
#pragma unroll
        for (int j = 0; j < 8; j++)
#pragma unroll
            for (int r = 0; r < 4; r++) acc[i][j][r] = 0.f;

    if (MODE == 4) { ldg_a(0); }
    load_chunk(0, 0);
    if (MODE == 4) { sts_a(0); }
    CP_WAIT_0();
    __syncthreads();

    for (int c = 0; c < nc; c++) {
        int s = c & 1;
        if (c + 1 < nc) {
            if (MODE == 4) ldg_a(c + 1);
            load_chunk(c + 1, s ^ 1);
        }

        uint32_t st = sbase + s * STAGE;
        uint32_t aHB = st, aLB = st + TILE_SZ;
        uint32_t bHB = st + (NT - (NPROD == 3 ? 2 : 1)) * TILE_SZ;
        uint32_t bLB = st + (NT - 1) * TILE_SZ;

#pragma unroll
        for (int ks = 0; ks < 2; ks++) {
            const int chcol = (ks * 2 + (lane >> 4)) * 16;
            uint32_t ah[2][4], al[2][4];
#pragma unroll
            for (int t = 0; t < 2; t++) {
                int row = wm * 32 + t * 16 + (lane & 15);
                uint32_t off = row * PITCH + chcol;
                ldsm4(ah[t][0], ah[t][1], ah[t][2], ah[t][3], aHB + off);
                if (NPROD >= 2)
                    ldsm4(al[t][0], al[t][1], al[t][2], al[t][3], aLB + off);
            }
            uint32_t bh[8][2], bl[8][2];
#pragma unroll
            for (int jj = 0; jj < 4; jj++) {
                int row = wn * 64 + jj * 16 + (lane & 15);
                uint32_t off = row * PITCH + chcol;
                uint32_t r0, r1, r2, r3;
                ldsm4(r0, r1, r2, r3, bHB + off);
                bh[jj * 2][0] = r0; bh[jj * 2][1] = r2;
                bh[jj * 2 + 1][0] = r1; bh[jj * 2 + 1][1] = r3;
                if (NPROD == 3 && !skipBl) {
                    ldsm4(r0, r1, r2, r3, bLB + off);
                    bl[jj * 2][0] = r0; bl[jj * 2][1] = r2;
                    bl[jj * 2 + 1][0] = r1; bl[jj * 2 + 1][1] = r3;
                }
            }
#pragma unroll
            for (int i = 0; i < 2; i++)
#pragma unroll
                for (int j = 0; j < 8; j++)
                    mma16816(acc[i][j], ah[i], bh[j]);
            if (NPROD >= 2) {
#pragma unroll
                for (int i = 0; i < 2; i++)
#pragma unroll
                    for (int j = 0; j < 8; j++)
                        mma16816(acc[i][j], al[i], bh[j]);
            }
            if (NPROD == 3) {
                if (!skipBl) {
#pragma unroll
                    for (int i = 0; i < 2; i++)
#pragma unroll
                        for (int j = 0; j < 8; j++)
                            mma16816(acc[i][j], ah[i], bl[j]);
                }
            }
        }
        if (MODE == 4 && c + 1 < nc) sts_a(s ^ 1);
        CP_WAIT_0();
        __syncthreads();
    }

    // --------- epilogue ---------
    if (MODE == 3 || MODE == 4) {
        float* o0 = p.outF + (long long)z * p.oBatch;
        const int mB = bm + wm * 32 + (lane >> 2);
        const int nB = bn + wn * 64 + (lane & 3) * 2;
        float rs[2][2] = {{0.f, 0.f}, {0.f, 0.f}};
#pragma unroll
        for (int i = 0; i < 2; i++)
#pragma unroll
            for (int j = 0; j < 8; j++) {
                int m = mB + i * 16, n = nB + j * 8;
                float v0 = acc[i][j][0], v1 = acc[i][j][1];
                float v2 = acc[i][j][2], v3 = acc[i][j][3];
                if (MODE == 3) {       // exp(logit); |logit| < 45, no shift needed
                    v0 = __expf(v0); v1 = __expf(v1);
                    v2 = __expf(v2); v3 = __expf(v3);
                    rs[i][0] += v0 + v1;
                    rs[i][1] += v2 + v3;
                }
                *(float2*)(o0 + (long long)m * p.oRow + n)       = make_float2(v0, v1);
                *(float2*)(o0 + (long long)(m + 8) * p.oRow + n) = make_float2(v2, v3);
            }
        if (MODE == 3) {
#pragma unroll
            for (int off = 1; off < 4; off <<= 1) {
#pragma unroll
                for (int i = 0; i < 2; i++) {
                    rs[i][0] += __shfl_xor_sync(0xFFFFFFFF, rs[i][0], off);
                    rs[i][1] += __shfl_xor_sync(0xFFFFFFFF, rs[i][1], off);
                }
            }
            float* spar = (float*)smem;            // [2][128]
            __syncthreads();
            if ((lane & 3) == 0) {
#pragma unroll
                for (int i = 0; i < 2; i++)
#pragma unroll
                    for (int hf = 0; hf < 2; hf++) {
                        int r = wm * 32 + i * 16 + hf * 8 + (lane >> 2);
                        spar[wn * 128 + r] = rs[i][hf];
                    }
            }
            __syncthreads();
            if (tid < 128) {
                float v = spar[tid] + spar[128 + tid];
                p.partials[((long long)z * 16 + blockIdx.x) * S_DIM + bm + tid] = v;
            }
        }
    } else {
        const int sel = bn >> 9;                    // 0=Q 1=K 2=V
        if (sel < 2) {
            __half* o0 = sel ? p.kh : p.qh;
            __half* o1 = p.ql;                      // lo only needed for Q
            const int mB = bm + wm * 32 + (lane >> 2);
            const int nW = wn * 64 + (lane & 3) * 2;
#pragma unroll
            for (int i = 0; i < 2; i++)
#pragma unroll
                for (int j = 0; j < 8; j++) {
                    int m = mB + i * 16;
                    int nl = (bn & 511) + nW + j * 8;
                    float b0 = p.bias[bn + nW + j * 8], b1 = p.bias[bn + nW + j * 8 + 1];
                    unsigned short h0, l0, h1, l1;
#pragma unroll
                    for (int hf = 0; hf < 2; hf++) {
                        int mm = m + hf * 8;
                        split2h(acc[i][j][hf * 2 + 0] + b0, h0, l0);
                        split2h(acc[i][j][hf * 2 + 1] + b1, h1, l1);
                        long long a = (long long)mm * H_DIM + nl;
                        *(ushort2*)(o0 + a) = make_ushort2(h0, h1);
                        if (sel == 0)
                            *(ushort2*)(o1 + a) = make_ushort2(l0, l1);
                    }
                }
        } else {
            // V: transposed fp16 out via smem staging [128][129] u32
            uint32_t* stg = (uint32_t*)smem;
            __syncthreads();
#pragma unroll
            for (int i = 0; i < 2; i++)
#pragma unroll
                for (int j = 0; j < 8; j++)
#pragma unroll
                    for (int r = 0; r < 4; r++) {
                        int ml = wm * 32 + i * 16 + (r >> 1) * 8 + (lane >> 2);
                        int nl = wn * 64 + j * 8 + (lane & 3) * 2 + (r & 1);
                        float v = acc[i][j][r] + p.bias[bn + nl];
                        stg[ml * 129 + nl] = (uint32_t)__half_as_ushort(__float2half_rn(v));
                    }
            __syncthreads();
            int col = tid >> 1, rch = (tid & 1) * 64;
            int n = (bn & 511) + col;
            long long base = (long long)n * NROWS + bm + rch;
#pragma unroll
            for (int r = 0; r < 64; r += 2) {
                uint32_t w0 = stg[(rch + r) * 129 + col];
                uint32_t w1 = stg[(rch + r + 1) * 129 + col];
                *(ushort2*)(p.vt + base + r) =
                    make_ushort2((unsigned short)w0, (unsigned short)w1);
            }
        }
    }
}

// ---------------- prep: pe table (fp32) + stacked weights/bias --------------
__global__ void prep_kernel(const float* __restrict__ Wq, const float* __restrict__ Wk,
                            const float* __restrict__ Wv,
                            const float* __restrict__ bq, const float* __restrict__ bk,
                            const float* __restrict__ bv,
                            float* __restrict__ pe, float* __restrict__ bias,
                            __half* __restrict__ wh, __half* __restrict__ wl) {
    int b = blockIdx.x, t = threadIdx.x;
    if (b < 4096) {
        int idx = b * 256 + t;
        int h = idx & (H_DIM - 1);
        int s = idx >> 9;
        int j = (h < H_DIM / 2) ? h : h - H_DIM / 2;
        float d   = expf((float)(2 * j) * (-9.210340371976184f / 512.0f));
        float ang = (float)s * d;
        pe[idx] = (h < H_DIM / 2) ? sinf(ang) : cosf(ang);
    } else if (b < 4096 + 3072) {
        int idx = (b - 4096) * 256 + t;
        int w = idx >> 18;
        int off = idx & 262143;
        const float* W = (w == 0) ? Wq : (w == 1) ? Wk : Wv;
        unsigned short h, l;
        split2h(W[off], h, l);
        wh[idx] = __ushort_as_half(h);
        wl[idx] = __ushort_as_half(l);
    } else {
        int i = (b - 4096 - 3072) * 256 + t;
        if (i < NSTACK)
            bias[i] = (i < 512) ? bq[i] : (i < 1024) ? bk[i - 512] : bv[i - 1024];
    }
}

// ---------------- conv_x: float4-vectorized -----------------------------------
__global__ void conv_x_kernel(const float* __restrict__ in, const float* __restrict__ pe,
                              __half* __restrict__ xh, __half* __restrict__ xl) {
    int i = blockIdx.x * blockDim.x + threadIdx.x;      // float4 index
    const int total4 = NROWS * H_DIM / 4;
    if (i >= total4) return;
    const int pe4 = S_DIM * H_DIM / 4;
    float4 a = ((const float4*)in)[i];
    float4 q = ((const float4*)pe)[i & (pe4 - 1)];
    a.x += q.x; a.y += q.y; a.z += q.z; a.w += q.w;
    unsigned short h0, l0, h1, l1, h2, l2, h3, l3;
    split2h(a.x, h0, l0); split2h(a.y, h1, l1);
    split2h(a.z, h2, l2); split2h(a.w, h3, l3);
    *(ushort4*)(xh + i * 4) = make_ushort4(h0, h1, h2, h3);
    *(ushort4*)(xl + i * 4) = make_ushort4(l0, l1, l2, l3);
}

// ---------------- rowinv: reduce 16 partials per row ------------------------
__global__ void rowinv_kernel(const float* __restrict__ pr, float* __restrict__ rinv) {
    int idx = blockIdx.x * blockDim.x + threadIdx.x;     // [0, 16384)
    if (idx >= B_DIM * S_DIM) return;
    int z = idx >> 11, m = idx & (S_DIM - 1);
    const float* base = pr + (long long)z * 16 * S_DIM + m;
    float s = 0.f;
#pragma unroll
    for (int j = 0; j < 16; j++) s += base[j * S_DIM];
    rinv[idx] = 1.f / s;
}

// ---------------- launch ----------------------------------------------------
extern "C" void kernel_launch(void* const* d_in, const int* in_sizes, int n_in,
                              void* d_out, int out_size) {
    const float* in_e = (const float*)d_in[0];
    const float* Wq   = (const float*)d_in[1];
    const float* bq   = (const float*)d_in[2];
    const float* Wk   = (const float*)d_in[3];
    const float* bk   = (const float*)d_in[4];
    const float* Wv   = (const float*)d_in[5];
    const float* bv   = (const float*)d_in[6];
    float* out = (float*)d_out;

    const int SMEM3 = 2 * 4 * TILE_SZ;          // 81920
    const int SMEM2 = 2 * 3 * TILE_SZ;          // 61440
    const int SMEM4 = 2 * 2 * TILE_SZ + 512;    // 41472
    cudaFuncSetAttribute(tc_gemm<3,0>, cudaFuncAttributeMaxDynamicSharedMemorySize, SMEM3);
    cudaFuncSetAttribute(tc_gemm<2,3>, cudaFuncAttributeMaxDynamicSharedMemorySize, SMEM2);
    cudaFuncSetAttribute(tc_gemm<1,4>, cudaFuncAttributeMaxDynamicSharedMemorySize, SMEM4);

#define SYM(v, s) void* v##_; cudaGetSymbolAddress(&v##_, s);
    SYM(pe, g_pe) SYM(bias, g_bias) SYM(xh, g_xh) SYM(xl, g_xl)
    SYM(wh, g_wh) SYM(wl, g_wl)
    SYM(qh, g_qh) SYM(ql, g_ql) SYM(kh, g_kh)
    SYM(vt, g_vt) SYM(sc, g_sc) SYM(pr, g_pr) SYM(rinv, g_rinv)
#undef SYM

    // 0: prep
    prep_kernel<<<4096 + 3072 + 6, 256>>>(Wq, Wk, Wv, bq, bk, bv,
        (float*)pe_, (float*)bias_, (__half*)wh_, (__half*)wl_);
    // 1: conv_x (vec4)
    conv_x_kernel<<<(NROWS * H_DIM / 4 + 255) / 256, 256>>>(in_e, (float*)pe_,
        (__half*)xh_, (__half*)xl_);

    GemmParams p;
    p.qh = (__half*)qh_; p.ql = (__half*)ql_;
    p.kh = (__half*)kh_; p.vt = (__half*)vt_;
    p.Af = nullptr; p.rinv = nullptr; p.partials = nullptr;

    // 2: fused QKV: Q/K 3-product, V 2-product
    p.Ah = (const __half*)xh_; p.Al = (const __half*)xl_;
    p.Bh = (const __half*)wh_; p.Bl = (const __half*)wl_;
    p.bias = (const float*)bias_;
    p.aBatch = 0; p.bBatch = 0; p.aRow = H_DIM; p.bRow = H_DIM; p.K = H_DIM;
    p.outF = nullptr; p.oBatch = 0; p.oRow = 0;
    dim3 gqkv(NSTACK / 128, NROWS / 128, 1);
    tc_gemm<3,0><<<gqkv, 256, SMEM3>>>(p);

    // 3: e = exp((qh+ql) @ kh^T), + per-CTA row partials
    p.Ah = (const __half*)qh_; p.Al = (const __half*)ql_;
    p.Bh = (const __half*)kh_; p.Bl = nullptr;
    p.partials = (float*)pr_;
    p.aBatch = (long long)S_DIM * H_DIM; p.bBatch = (long long)S_DIM * H_DIM;
    p.aRow = H_DIM; p.bRow = H_DIM; p.K = H_DIM;
    p.outF = (float*)sc_;
    p.oBatch = (long long)S_DIM * S_DIM; p.oRow = S_DIM;
    dim3 gs(S_DIM / 128, S_DIM / 128, B_DIM);
    tc_gemm<2,3><<<gs, 256, SMEM2>>>(p);

    // 4: rowinv = 1 / rowsum
    rowinv_kernel<<<(B_DIM * S_DIM + 255) / 256, 256>>>((const float*)pr_, (float*)rinv_);

    // 5: out = (e * rowinv) @ v  (MODE 4) — ncu -s 5 target
    p.Ah = nullptr; p.Al = nullptr;
    p.Af = (const float*)sc_; p.rinv = (const float*)rinv_;
    p.Bh = (const __half*)vt_; p.Bl = nullptr;
    p.partials = nullptr;
    p.aBatch = (long long)S_DIM * S_DIM; p.bBatch = S_DIM;
    p.aRow = S_DIM; p.bRow = NROWS; p.K = S_DIM;
    p.outF = out;
    p.oBatch = (long long)S_DIM * H_DIM; p.oRow = H_DIM;
    dim3 go(H_DIM / 128, S_DIM / 128, B_DIM);
    tc_gemm<1,4><<<go, 256, SMEM4>>>(p);
}